// round 15
// baseline (speedup 1.0000x reference)
#include <cuda_runtime.h>
#include <math.h>

#define N_NODES 20000
#define N_EDGES 200000
#define HCH 128
#define NB_NODE 625      // 20000/32
#define NB_N64 313       // ceil(20000/64)
#define NB_E8 25000      // 200000/8

typedef unsigned long long ull;

// ---------------- scratch (device globals; allocation-free) ----------------
// g_v uses SECTION-MAJOR layout: [node][s*128 + h*16 + d] (s = x|v1|v2)
__device__ __align__(16) float g_q[N_NODES * HCH];
__device__ __align__(16) float g_k[N_NODES * HCH];
__device__ __align__(16) float g_v[N_NODES * 3 * HCH];
__device__ __align__(16) float g_vec3[N_NODES * 3 * HCH];
__device__ __align__(16) float g_vdot[N_NODES * HCH];
__device__ __align__(16) float g_xagg[N_NODES * HCH];
__device__ __align__(16) float g_vagg[N_NODES * 3 * HCH];

__device__ __forceinline__ float silu_f(float v) {
    return v / (1.f + __expf(-v));
}
__device__ __forceinline__ float cutoff_f(float r) {
    return (r < 10.f) ? 0.5f * (__cosf(r * 0.31415926535897931f) + 1.f) : 0.f;
}

// ---- packed f32x2 helpers ----
__device__ __forceinline__ ull pack2(float x, float y) {
    ull r; asm("mov.b64 %0, {%1, %2};" : "=l"(r) : "f"(x), "f"(y)); return r;
}
__device__ __forceinline__ float2 unpack2(ull v) {
    float x, y; asm("mov.b64 {%0, %1}, %2;" : "=f"(x), "=f"(y) : "l"(v));
    return make_float2(x, y);
}
__device__ __forceinline__ void ffma2(ull& a, ull b, ull c) {
    asm("fma.rn.f32x2 %0, %1, %2, %0;" : "+l"(a) : "l"(b), "l"(c));
}
__device__ __forceinline__ void red4(float* p, float4 v) {
    asm volatile("red.global.add.v4.f32 [%0], {%1, %2, %3, %4};"
                 :: "l"(p), "f"(v.x), "f"(v.y), "f"(v.z), "f"(v.w) : "memory");
}

// ---- double-buffered weight staging: 32x128 chunk via registers ----
__device__ __forceinline__ void ldgW(float4* t, const float* __restrict__ W,
                                     int kc, int ld, int coff, int tid) {
    #pragma unroll
    for (int i = 0; i < 4; i++) {
        int idx = tid + i * 256;
        int r = idx >> 5, c4 = idx & 31;
        t[i] = *reinterpret_cast<const float4*>(&W[(kc + r) * ld + coff + c4 * 4]);
    }
}
__device__ __forceinline__ void stsW(float* sB, const float4* t, int tid) {
    #pragma unroll
    for (int i = 0; i < 4; i++)
        reinterpret_cast<float4*>(sB)[tid + i * 256] = t[i];
}

// packed inner loop: 32 k-steps, 16 cols, TWO nodes per thread
__device__ __forceinline__ void gemm16p32x2(const float* __restrict__ aR0,
                                            const float* __restrict__ aR1,
                                            int kc, const float* __restrict__ sB,
                                            int c0, ull* accA, ull* accB) {
    #pragma unroll 2
    for (int k = 0; k < 32; k++) {
        float a = aR0[kc + k], b = aR1[kc + k];
        ull a2 = pack2(a, a), b2 = pack2(b, b);
        const ulonglong2* b4 =
            reinterpret_cast<const ulonglong2*>(sB + k * 128 + c0);
        ulonglong2 q0 = b4[0], q1 = b4[1], q2 = b4[2], q3 = b4[3];
        ffma2(accA[0], a2, q0.x); ffma2(accA[1], a2, q0.y);
        ffma2(accA[2], a2, q1.x); ffma2(accA[3], a2, q1.y);
        ffma2(accA[4], a2, q2.x); ffma2(accA[5], a2, q2.y);
        ffma2(accA[6], a2, q3.x); ffma2(accA[7], a2, q3.y);
        ffma2(accB[0], b2, q0.x); ffma2(accB[1], b2, q0.y);
        ffma2(accB[2], b2, q1.x); ffma2(accB[3], b2, q1.y);
        ffma2(accB[4], b2, q2.x); ffma2(accB[5], b2, q2.y);
        ffma2(accB[6], b2, q3.x); ffma2(accB[7], b2, q3.y);
    }
}

__device__ __forceinline__ void unpack16(const ull* acc, float* o) {
    #pragma unroll
    for (int i = 0; i < 8; i++) {
        float2 f = unpack2(acc[i]);
        o[2 * i] = f.x; o[2 * i + 1] = f.y;
    }
}

// 64-node GEMM with direct register->global stores.
// permV: remap output column block f0 -> s*128 + h*16 (section-major V).
__device__ __forceinline__ void gemm_store_direct(
    const float* __restrict__ sH, const float* __restrict__ W,
    const float* __restrict__ B, float* __restrict__ OUT, int Ctot,
    float* sB0, float* sB1, int n0, int tid, int lane, int c0, int permV) {
    for (int ct = 0; ct < Ctot; ct += 128) {
        ull acc[16];
        #pragma unroll
        for (int j = 0; j < 16; j++) acc[j] = 0ull;

        float4 t[4];
        ldgW(t, W, 0, Ctot, ct, tid);
        __syncthreads();               // prior readers of sB0 done / sH visible
        stsW(sB0, t, tid);
        #pragma unroll
        for (int kc = 0; kc < 128; kc += 32) {
            __syncthreads();
            if (kc < 96) ldgW(t, W, kc + 32, Ctot, ct, tid);
            float* cur = ((kc >> 5) & 1) ? sB1 : sB0;
            gemm16p32x2(sH + lane * 129, sH + (lane + 32) * 129, kc, cur, c0,
                        acc, acc + 8);
            if (kc < 96) stsW(((kc >> 5) & 1) ? sB0 : sB1, t, tid);
        }
        float oa[16], ob[16];
        unpack16(acc, oa);
        unpack16(acc + 8, ob);
        int na0 = n0 + lane, na1 = n0 + lane + 32;
        #pragma unroll
        for (int j = 0; j < 16; j++) {
            float bi = __ldg(&B[ct + c0 + j]);
            oa[j] += bi; ob[j] += bi;
        }
        int g0 = ct + c0;
        if (permV) {
            int h = g0 / 48, r = g0 - h * 48, s = r >> 4;
            g0 = s * 128 + h * 16;
        }
        if (na0 < N_NODES) {
            float4* d = reinterpret_cast<float4*>(OUT + na0 * Ctot + g0);
            d[0] = make_float4(oa[0], oa[1], oa[2], oa[3]);
            d[1] = make_float4(oa[4], oa[5], oa[6], oa[7]);
            d[2] = make_float4(oa[8], oa[9], oa[10], oa[11]);
            d[3] = make_float4(oa[12], oa[13], oa[14], oa[15]);
        }
        if (na1 < N_NODES) {
            float4* d = reinterpret_cast<float4*>(OUT + na1 * Ctot + g0);
            d[0] = make_float4(ob[0], ob[1], ob[2], ob[3]);
            d[1] = make_float4(ob[4], ob[5], ob[6], ob[7]);
            d[2] = make_float4(ob[8], ob[9], ob[10], ob[11]);
            d[3] = make_float4(ob[12], ob[13], ob[14], ob[15]);
        }
    }
}

// single-buffer loadB, vectorized: 4x LDG.128 + 4x STS.128 per thread
__device__ __forceinline__ void loadB32(float* sB, const float* __restrict__ W,
                                        int kc, int ld, int coff, int tid) {
    #pragma unroll
    for (int i = 0; i < 4; i++) {
        int idx = tid + i * 256;
        int r = idx >> 5, c4 = idx & 31;
        reinterpret_cast<float4*>(sB)[idx] =
            *reinterpret_cast<const float4*>(&W[(kc + r) * ld + coff + c4 * 4]);
    }
}

// ---------------- kernel 0: zero aggregation buffers ----------------
__global__ void zero_kernel() {
    int i = blockIdx.x * blockDim.x + threadIdx.x;
    int stride = gridDim.x * blockDim.x;
    float4 z = make_float4(0.f, 0.f, 0.f, 0.f);
    float4* xa = reinterpret_cast<float4*>(g_xagg);
    float4* va = reinterpret_cast<float4*>(g_vagg);
    for (int k = i; k < N_NODES * 32; k += stride) xa[k] = z;
    for (int k = i; k < N_NODES * 96; k += stride) va[k] = z;
}

// -------- kernel 1: mix MLP + LN + q/k/v. 64-node tiles, 2 nodes/thread ----
__global__ void __launch_bounds__(256, 3) node_qkv_kernel(
    const float* __restrict__ x, const float* __restrict__ na,
    const float* __restrict__ w1, const float* __restrict__ b1,
    const float* __restrict__ w2, const float* __restrict__ b2,
    const float* __restrict__ lng, const float* __restrict__ lnb,
    const float* __restrict__ qw, const float* __restrict__ qb,
    const float* __restrict__ kw, const float* __restrict__ kb,
    const float* __restrict__ vw, const float* __restrict__ vb) {
    extern __shared__ float sm[];
    float* sAH  = sm;                  // 64*129 = 8256
    float* sB0  = sm + 8256;           // 4096
    float* sB1  = sm + 12352;          // 4096
    float* sRed = sm + 16448;          // 1152

    int tid = threadIdx.x, lane = tid & 31, warp = tid >> 5;
    int c0 = warp * 16;
    int n0 = blockIdx.x * 64;

    for (int idx = tid; idx < 8192; idx += 256) {
        int node = idx >> 7, k = idx & 127;
        int gn = min(n0 + node, N_NODES - 1);
        sAH[node * 129 + k] = x[gn * 128 + k];
    }

    // GEMM1 pass A: h1 += x @ w1[0:128]
    ull acc[16];
    #pragma unroll
    for (int j = 0; j < 16; j++) acc[j] = 0ull;
    float4 t[4];
    ldgW(t, w1, 0, 128, 0, tid);
    stsW(sB0, t, tid);
    #pragma unroll
    for (int kc = 0; kc < 128; kc += 32) {
        __syncthreads();
        ldgW(t, w1, kc + 32, 128, 0, tid);
        float* cur = ((kc >> 5) & 1) ? sB1 : sB0;
        gemm16p32x2(sAH + lane * 129, sAH + (lane + 32) * 129, kc, cur, c0,
                    acc, acc + 8);
        stsW(((kc >> 5) & 1) ? sB0 : sB1, t, tid);
    }
    __syncthreads();
    for (int idx = tid; idx < 8192; idx += 256) {
        int node = idx >> 7, k = idx & 127;
        int gn = min(n0 + node, N_NODES - 1);
        sAH[node * 129 + k] = na[gn * 128 + k];
    }
    // GEMM1 pass B: h1 += na @ w1[128:256]
    #pragma unroll
    for (int kc = 128; kc < 256; kc += 32) {
        __syncthreads();
        if (kc < 224) ldgW(t, w1, kc + 32, 128, 0, tid);
        float* cur = ((kc >> 5) & 1) ? sB1 : sB0;
        gemm16p32x2(sAH + lane * 129, sAH + (lane + 32) * 129, kc - 128, cur,
                    c0, acc, acc + 8);
        if (kc < 224) stsW(((kc >> 5) & 1) ? sB0 : sB1, t, tid);
    }
    float ha[16], hb[16];
    unpack16(acc, ha);
    unpack16(acc + 8, hb);
    __syncthreads();
    #pragma unroll
    for (int j = 0; j < 16; j++) {
        float bi = __ldg(&b1[c0 + j]);
        sAH[lane * 129 + c0 + j] = silu_f(ha[j] + bi);
        sAH[(lane + 32) * 129 + c0 + j] = silu_f(hb[j] + bi);
    }

    // GEMM2: h = h1 @ w2 + b2
    #pragma unroll
    for (int j = 0; j < 16; j++) acc[j] = 0ull;
    ldgW(t, w2, 0, 128, 0, tid);
    stsW(sB0, t, tid);
    #pragma unroll
    for (int kc = 0; kc < 128; kc += 32) {
        __syncthreads();
        if (kc < 96) ldgW(t, w2, kc + 32, 128, 0, tid);
        float* cur = ((kc >> 5) & 1) ? sB1 : sB0;
        gemm16p32x2(sAH + lane * 129, sAH + (lane + 32) * 129, kc, cur, c0,
                    acc, acc + 8);
        if (kc < 96) stsW(((kc >> 5) & 1) ? sB0 : sB1, t, tid);
    }
    unpack16(acc, ha);
    unpack16(acc + 8, hb);
    #pragma unroll
    for (int j = 0; j < 16; j++) {
        float bi = __ldg(&b2[c0 + j]);
        ha[j] += bi; hb[j] += bi;
    }

    // LayerNorm
    float sa = 0.f, sa2 = 0.f, sb = 0.f, sb2 = 0.f;
    #pragma unroll
    for (int j = 0; j < 16; j++) {
        sa += ha[j]; sa2 += ha[j] * ha[j];
        sb += hb[j]; sb2 += hb[j] * hb[j];
    }
    sRed[warp * 64 + lane] = sa;
    sRed[warp * 64 + 32 + lane] = sb;
    sRed[512 + warp * 64 + lane] = sa2;
    sRed[512 + warp * 64 + 32 + lane] = sb2;
    __syncthreads();
    if (tid < 64) {
        float ss = 0.f, qq = 0.f;
        #pragma unroll
        for (int w = 0; w < 8; w++) {
            ss += sRed[w * 64 + tid];
            qq += sRed[512 + w * 64 + tid];
        }
        float mu = ss * (1.f / 128.f);
        float var = qq * (1.f / 128.f) - mu * mu;
        sRed[1024 + tid] = mu;
        sRed[1088 + tid] = rsqrtf(var + 1e-5f);
    }
    __syncthreads();
    {
        float mua = sRed[1024 + lane], rsa = sRed[1088 + lane];
        float mub = sRed[1024 + 32 + lane], rsb = sRed[1088 + 32 + lane];
        #pragma unroll
        for (int j = 0; j < 16; j++) {
            float g = __ldg(&lng[c0 + j]), bi = __ldg(&lnb[c0 + j]);
            sAH[lane * 129 + c0 + j] = (ha[j] - mua) * rsa * g + bi;
            sAH[(lane + 32) * 129 + c0 + j] = (hb[j] - mub) * rsb * g + bi;
        }
    }

    gemm_store_direct(sAH, qw, qb, g_q, 128, sB0, sB1, n0, tid, lane, c0, 0);
    gemm_store_direct(sAH, kw, kb, g_k, 128, sB0, sB1, n0, tid, lane, c0, 0);
    gemm_store_direct(sAH, vw, vb, g_v, 384, sB0, sB1, n0, tid, lane, c0, 1);
}

// ---------------- kernel 2: vec projection -> vec_dot, vec3 (66KB) --------
__global__ void __launch_bounds__(256) node_vec_kernel(
    const float* __restrict__ vec, const float* __restrict__ vecw) {
    extern __shared__ float sm[];
    float* sA = sm;                // 96*129 = 12384
    float* sB = sA + 12384;        // 4096

    int tid = threadIdx.x, lane = tid & 31, warp = tid >> 5;
    int c0 = warp * 16;
    int n0 = blockIdx.x * 32;

    for (int idx = tid; idx < 32 * 384; idx += 256) {
        int node = idx / 384;
        int rem = idx - node * 384;
        int c = rem >> 7, k = rem & 127;
        sA[(c * 32 + node) * 129 + k] = vec[(n0 + node) * 384 + rem];
    }

    float vp1[3][16];

    for (int reg = 0; reg < 3; reg++) {
        ull acc[3][8];
        #pragma unroll
        for (int c = 0; c < 3; c++)
            #pragma unroll
            for (int j = 0; j < 8; j++) acc[c][j] = 0ull;

        for (int kc = 0; kc < 128; kc += 32) {
            __syncthreads();
            loadB32(sB, vecw, kc, 384, reg * 128, tid);
            __syncthreads();
            #pragma unroll 2
            for (int k = 0; k < 32; k++) {
                float f0 = sA[(0 * 32 + lane) * 129 + kc + k];
                float f1 = sA[(1 * 32 + lane) * 129 + kc + k];
                float f2v = sA[(2 * 32 + lane) * 129 + kc + k];
                ull a0 = pack2(f0, f0), a1 = pack2(f1, f1), a2 = pack2(f2v, f2v);
                const ulonglong2* b4 =
                    reinterpret_cast<const ulonglong2*>(sB + k * 128 + c0);
                ulonglong2 q0 = b4[0], q1 = b4[1], q2 = b4[2], q3 = b4[3];
                ffma2(acc[0][0], a0, q0.x); ffma2(acc[0][1], a0, q0.y);
                ffma2(acc[0][2], a0, q1.x); ffma2(acc[0][3], a0, q1.y);
                ffma2(acc[0][4], a0, q2.x); ffma2(acc[0][5], a0, q2.y);
                ffma2(acc[0][6], a0, q3.x); ffma2(acc[0][7], a0, q3.y);
                ffma2(acc[1][0], a1, q0.x); ffma2(acc[1][1], a1, q0.y);
                ffma2(acc[1][2], a1, q1.x); ffma2(acc[1][3], a1, q1.y);
                ffma2(acc[1][4], a1, q2.x); ffma2(acc[1][5], a1, q2.y);
                ffma2(acc[1][6], a1, q3.x); ffma2(acc[1][7], a1, q3.y);
                ffma2(acc[2][0], a2, q0.x); ffma2(acc[2][1], a2, q0.y);
                ffma2(acc[2][2], a2, q1.x); ffma2(acc[2][3], a2, q1.y);
                ffma2(acc[2][4], a2, q2.x); ffma2(acc[2][5], a2, q2.y);
                ffma2(acc[2][6], a2, q3.x); ffma2(acc[2][7], a2, q3.y);
            }
        }

        float af[3][16];
        unpack16(acc[0], af[0]);
        unpack16(acc[1], af[1]);
        unpack16(acc[2], af[2]);

        if (reg == 0) {
            #pragma unroll
            for (int c = 0; c < 3; c++)
                #pragma unroll
                for (int j = 0; j < 16; j++) vp1[c][j] = af[c][j];
        } else if (reg == 1) {
            float vd[16];
            #pragma unroll
            for (int j = 0; j < 16; j++)
                vd[j] = vp1[0][j] * af[0][j] + vp1[1][j] * af[1][j] +
                        vp1[2][j] * af[2][j];
            float4* dst =
                reinterpret_cast<float4*>(g_vdot + (n0 + lane) * 128 + c0);
            dst[0] = make_float4(vd[0], vd[1], vd[2], vd[3]);
            dst[1] = make_float4(vd[4], vd[5], vd[6], vd[7]);
            dst[2] = make_float4(vd[8], vd[9], vd[10], vd[11]);
            dst[3] = make_float4(vd[12], vd[13], vd[14], vd[15]);
        } else {
            // vec3: direct register->global float4 stores (own node = lane)
            #pragma unroll
            for (int c = 0; c < 3; c++) {
                float4* dst = reinterpret_cast<float4*>(
                    g_vec3 + (n0 + lane) * 384 + c * 128 + c0);
                dst[0] = make_float4(af[c][0], af[c][1], af[c][2], af[c][3]);
                dst[1] = make_float4(af[c][4], af[c][5], af[c][6], af[c][7]);
                dst[2] = make_float4(af[c][8], af[c][9], af[c][10], af[c][11]);
                dst[3] = make_float4(af[c][12], af[c][13], af[c][14], af[c][15]);
            }
        }
    }
}

// ---------------- kernel 3: edges (section-major v/dv reads) --------------
__global__ void __launch_bounds__(128) edge_kernel(
    const int* __restrict__ ei, const float* __restrict__ rij,
    const float* __restrict__ fij, const float* __restrict__ dij,
    const float* __restrict__ dkw, const float* __restrict__ dkb,
    const float* __restrict__ dvw, const float* __restrict__ dvb,
    const float* __restrict__ vec) {
    __shared__ __align__(16) float sDK[8 * 128];   // 4096 B
    __shared__ __align__(16) float sDV[8 * 384];   // 12288 B (first 4KB = sF2)
    __shared__ int sJ[8], sI[8];
    __shared__ float sR[8];
    __shared__ float sD[8][3];

    ull* sF2 = reinterpret_cast<ull*>(sDV);        // alias: 512 ull = 4096 B

    int tid = threadIdx.x;
    int e0 = blockIdx.x * 8;

    for (int idx = tid; idx < 512; idx += 128) {
        int r = idx >> 3, e = idx & 7;
        float f = fij[(e0 + e) * 64 + r];
        sF2[idx] = pack2(f, f);
    }
    if (tid < 8) {
        sJ[tid] = ei[e0 + tid];
        sI[tid] = ei[N_EDGES + e0 + tid];
        sR[tid] = rij[e0 + tid];
    }
    if (tid < 24) sD[tid / 3][tid % 3] = dij[e0 * 3 + tid];
    __syncthreads();

    // phase 1: fused (dk|dv) GEMM: 64 x 512, thread owns 4 output channels.
    ull acc[16];
    #pragma unroll
    for (int j = 0; j < 16; j++) acc[j] = 0ull;

    const float* wbase;
    int wstr;
    if (tid < 32) { wbase = dkw + tid * 4; wstr = 128; }
    else          { wbase = dvw + (tid - 32) * 4; wstr = 384; }

    #pragma unroll 2
    for (int r = 0; r < 64; r++) {
        ulonglong2 w =
            *reinterpret_cast<const ulonglong2*>(wbase + r * wstr);
        const ulonglong2* fp2 =
            reinterpret_cast<const ulonglong2*>(&sF2[r * 8]);
        #pragma unroll
        for (int ep = 0; ep < 4; ep++) {
            ulonglong2 ff = fp2[ep];
            ffma2(acc[2 * ep],     ff.x, w.x);
            ffma2(acc[8 + 2 * ep], ff.x, w.y);
            ffma2(acc[2 * ep + 1],     ff.y, w.x);
            ffma2(acc[8 + 2 * ep + 1], ff.y, w.y);
        }
    }
    __syncthreads();   // sF2 reads done before epilogue overwrites sDV[0:4KB]

    float4 bia;
    if (tid < 32) bia = *reinterpret_cast<const float4*>(dkb + tid * 4);
    else          bia = *reinterpret_cast<const float4*>(dvb + (tid - 32) * 4);

    // dv stores remapped to section-major: f = h*48+s*16+d -> s*128+h*16+d
    int gbase = 0;
    if (tid >= 32) {
        int f = (tid - 32) * 4;
        int h = f / 48, r = f - h * 48, s = r >> 4, d = r & 15;
        gbase = s * 128 + h * 16 + d;
    }

    #pragma unroll
    for (int e = 0; e < 8; e++) {
        float2 lo = unpack2(acc[e]);
        float2 hi = unpack2(acc[8 + e]);
        float4 ov;
        ov.x = silu_f(lo.x + bia.x);
        ov.y = silu_f(lo.y + bia.y);
        ov.z = silu_f(hi.x + bia.z);
        ov.w = silu_f(hi.y + bia.w);
        if (tid < 32)
            *reinterpret_cast<float4*>(&sDK[e * 128 + tid * 4]) = ov;
        else
            *reinterpret_cast<float4*>(&sDV[e * 384 + gbase]) = ov;
    }
    __syncthreads();

    // phase 2: attention + messages + vectorized reductions (section-major)
    int lane = tid & 31;
    int ch = lane * 4;     // = head*16 + d, contiguous across warp

    #pragma unroll
    for (int es = 0; es < 2; es++) {
        int e = (tid >> 5) + es * 4;
        int j = sJ[e], i = sI[e];

        float4 q4 = *reinterpret_cast<const float4*>(g_q + i * 128 + ch);
        float4 k4 = *reinterpret_cast<const float4*>(g_k + j * 128 + ch);
        float4 dk4 = *reinterpret_cast<const float4*>(&sDK[e * 128 + ch]);
        float t = q4.x * k4.x * dk4.x + q4.y * k4.y * dk4.y +
                  q4.z * k4.z * dk4.z + q4.w * k4.w * dk4.w;
        t += __shfl_xor_sync(0xffffffffu, t, 1);
        t += __shfl_xor_sync(0xffffffffu, t, 2);
        float attn = silu_f(t) * cutoff_f(sR[e]);

        const float* vb = g_v + j * 384;   // section-major
        float4 v0 = *reinterpret_cast<const float4*>(vb + ch);
        float4 v1 = *reinterpret_cast<const float4*>(vb + 128 + ch);
        float4 v2 = *reinterpret_cast<const float4*>(vb + 256 + ch);
        float4 dv0 = *reinterpret_cast<const float4*>(&sDV[e * 384 + ch]);
        float4 dv1 = *reinterpret_cast<const float4*>(&sDV[e * 384 + 128 + ch]);
        float4 dv2 = *reinterpret_cast<const float4*>(&sDV[e * 384 + 256 + ch]);

        float4 xm;
        xm.x = v0.x * dv0.x * attn; xm.y = v0.y * dv0.y * attn;
        xm.z = v0.z * dv0.z * attn; xm.w = v0.w * dv0.w * attn;
        red4(g_xagg + i * 128 + ch, xm);

        float4 v1m, v2m;
        v1m.x = v1.x * dv1.x; v1m.y = v1.y * dv1.y;
        v1m.z = v1.z * dv1.z; v1m.w = v1.w * dv1.w;
        v2m.x = v2.x * dv2.x; v2m.y = v2.y * dv2.y;
        v2m.z = v2.z * dv2.z; v2m.w = v2.w * dv2.w;

        const float* vecb = vec + j * 384;
        #pragma unroll
        for (int c = 0; c < 3; c++) {
            float dc = sD[e][c];
            float4 vc =
                *reinterpret_cast<const float4*>(vecb + c * 128 + ch);
            float4 m;
            m.x = vc.x * v1m.x + v2m.x * dc;
            m.y = vc.y * v1m.y + v2m.y * dc;
            m.z = vc.z * v1m.z + v2m.z * dc;
            m.w = vc.w * v1m.w + v2m.w * dc;
            red4(g_vagg + i * 384 + c * 128 + ch, m);
        }
    }
}

// -------- kernel 4: output. 64-node tiles, 2 nodes/thread, db (98.8KB) ----
__global__ void __launch_bounds__(256, 2) out_kernel(
    const float* __restrict__ ow, const float* __restrict__ obv,
    float* __restrict__ out) {
    extern __shared__ float sm[];
    float* sA  = sm;                  // 64*129 = 8256 (xagg)
    float* sO1 = sm + 8256;           // 8256
    float* sB0 = sm + 16512;          // 4096
    float* sB1 = sm + 20608;          // 4096

    int tid = threadIdx.x, lane = tid & 31, warp = tid >> 5;
    int c0 = warp * 16;
    int n0 = blockIdx.x * 64;
    int na0 = n0 + lane, na1 = n0 + lane + 32;

    for (int idx = tid; idx < 8192; idx += 256) {
        int node = idx >> 7, k = idx & 127;
        int gn = min(n0 + node, N_NODES - 1);
        sA[node * 129 + k] = g_xagg[gn * 128 + k];
    }

    float dxa[16], dxb[16];

    for (int reg = 0; reg < 3; reg++) {
        ull acc[16];
        #pragma unroll
        for (int j = 0; j < 16; j++) acc[j] = 0ull;

        float4 t[4];
        ldgW(t, ow, 0, 384, reg * 128, tid);
        __syncthreads();   // staging visible (first) / prior sB0 readers done
        stsW(sB0, t, tid);
        #pragma unroll
        for (int kc = 0; kc < 128; kc += 32) {
            __syncthreads();
            if (kc < 96) ldgW(t, ow, kc + 32, 384, reg * 128, tid);
            float* cur = ((kc >> 5) & 1) ? sB1 : sB0;
            gemm16p32x2(sA + lane * 129, sA + (lane + 32) * 129, kc, cur, c0,
                        acc, acc + 8);
            if (kc < 96) stsW(((kc >> 5) & 1) ? sB0 : sB1, t, tid);
        }
        float oa[16], obf[16];
        unpack16(acc, oa);
        unpack16(acc + 8, obf);
        #pragma unroll
        for (int j = 0; j < 16; j++) {
            float bi = __ldg(&obv[reg * 128 + c0 + j]);
            oa[j] += bi; obf[j] += bi;
        }

        if (reg == 0) {
            // o1 -> smem for the distributed dvec epilogue
            #pragma unroll
            for (int j = 0; j < 16; j++) {
                sO1[lane * 129 + c0 + j] = oa[j];
                sO1[(lane + 32) * 129 + c0 + j] = obf[j];
            }
        } else if (reg == 1) {
            // dx = vdot * o2 (direct global loads of own rows)
            int ga = min(na0, N_NODES - 1), gb = min(na1, N_NODES - 1);
            const float4* va =
                reinterpret_cast<const float4*>(g_vdot + ga * 128 + c0);
            const float4* vbp =
                reinterpret_cast<const float4*>(g_vdot + gb * 128 + c0);
            #pragma unroll
            for (int q = 0; q < 4; q++) {
                float4 v = va[q];
                dxa[4 * q] = v.x * oa[4 * q];
                dxa[4 * q + 1] = v.y * oa[4 * q + 1];
                dxa[4 * q + 2] = v.z * oa[4 * q + 2];
                dxa[4 * q + 3] = v.w * oa[4 * q + 3];
                float4 w = vbp[q];
                dxb[4 * q] = w.x * obf[4 * q];
                dxb[4 * q + 1] = w.y * obf[4 * q + 1];
                dxb[4 * q + 2] = w.z * obf[4 * q + 2];
                dxb[4 * q + 3] = w.w * obf[4 * q + 3];
            }
        } else {
            // dx += o3; store
            #pragma unroll
            for (int j = 0; j < 16; j++) { dxa[j] += oa[j]; dxb[j] += obf[j]; }
            if (na0 < N_NODES) {
                float4* d =
                    reinterpret_cast<float4*>(out + na0 * 128 + c0);
                d[0] = make_float4(dxa[0], dxa[1], dxa[2], dxa[3]);
                d[1] = make_float4(dxa[4], dxa[5], dxa[6], dxa[7]);
                d[2] = make_float4(dxa[8], dxa[9], dxa[10], dxa[11]);
                d[3] = make_float4(dxa[12], dxa[13], dxa[14], dxa[15]);
            }
            if (na1 < N_NODES) {
                float4* d =
                    reinterpret_cast<float4*>(out + na1 * 128 + c0);
                d[0] = make_float4(dxb[0], dxb[1], dxb[2], dxb[3]);
                d[1] = make_float4(dxb[4], dxb[5], dxb[6], dxb[7]);
                d[2] = make_float4(dxb[8], dxb[9], dxb[10], dxb[11]);
                d[3] = make_float4(dxb[12], dxb[13], dxb[14], dxb[15]);
            }
        }
    }
    __syncthreads();   // sO1 fully written before distributed reads

    // dvec epilogue
    const int base = N_NODES * 128;
    for (int idx = tid; idx < 64 * 384; idx += 256) {
        int node = idx / 384;
        int rem = idx - node * 384;
        int col = rem & 127;
        if (n0 + node < N_NODES) {
            int g = (n0 + node) * 384 + rem;
            out[base + g] = g_vec3[g] * sO1[node * 129 + col] + g_vagg[g];
        }
    }
}

// ---------------- launch ----------------
extern "C" void kernel_launch(void* const* d_in, const int* in_sizes, int n_in,
                              void* d_out, int out_size) {
    const float* x    = (const float*)d_in[0];
    const float* vec  = (const float*)d_in[1];
    const float* na   = (const float*)d_in[2];
    const int*   ei   = (const int*)d_in[3];
    const float* rij  = (const float*)d_in[4];
    const float* fij  = (const float*)d_in[5];
    const float* dij  = (const float*)d_in[6];
    const float* w1   = (const float*)d_in[7];
    const float* b1   = (const float*)d_in[8];
    const float* w2   = (const float*)d_in[9];
    const float* b2   = (const float*)d_in[10];
    const float* lng  = (const float*)d_in[11];
    const float* lnb  = (const float*)d_in[12];
    const float* qw   = (const float*)d_in[13];
    const float* qb   = (const float*)d_in[14];
    const float* kw   = (const float*)d_in[15];
    const float* kb   = (const float*)d_in[16];
    const float* vw   = (const float*)d_in[17];
    const float* vb   = (const float*)d_in[18];
    const float* ow   = (const float*)d_in[19];
    const float* ob   = (const float*)d_in[20];
    const float* vecw = (const float*)d_in[21];
    const float* dkw  = (const float*)d_in[22];
    const float* dkb  = (const float*)d_in[23];
    const float* dvw  = (const float*)d_in[24];
    const float* dvb  = (const float*)d_in[25];
    float* out = (float*)d_out;

    const int SM_QKV = (8256 + 4096 + 4096 + 1152) * 4;  // 70400
    const int SM_VEC = (12384 + 4096) * 4;               // 65920
    const int SM_OUT = (8256 + 8256 + 4096 + 4096) * 4;  // 98816

    cudaFuncSetAttribute(node_qkv_kernel,
                         cudaFuncAttributeMaxDynamicSharedMemorySize, SM_QKV);
    cudaFuncSetAttribute(node_vec_kernel,
                         cudaFuncAttributeMaxDynamicSharedMemorySize, SM_VEC);
    cudaFuncSetAttribute(out_kernel,
                         cudaFuncAttributeMaxDynamicSharedMemorySize, SM_OUT);

    // R9 schedule (best): s2 runs zero then node_vec concurrent with qkv.
    cudaStream_t s2;
    cudaStreamCreateWithFlags(&s2, cudaStreamNonBlocking);
    cudaEvent_t eFork, eZero, eVec;
    cudaEventCreateWithFlags(&eFork, cudaEventDisableTiming);
    cudaEventCreateWithFlags(&eZero, cudaEventDisableTiming);
    cudaEventCreateWithFlags(&eVec, cudaEventDisableTiming);

    cudaEventRecord(eFork, 0);
    cudaStreamWaitEvent(s2, eFork, 0);
    zero_kernel<<<2560, 256, 0, s2>>>();
    cudaEventRecord(eZero, s2);
    node_vec_kernel<<<NB_NODE, 256, SM_VEC, s2>>>(vec, vecw);
    cudaEventRecord(eVec, s2);

    node_qkv_kernel<<<NB_N64, 256, SM_QKV>>>(x, na, w1, b1, w2, b2, lng, lnb,
                                             qw, qb, kw, kb, vw, vb);
    cudaStreamWaitEvent(0, eZero, 0);
    edge_kernel<<<NB_E8, 128>>>(ei, rij, fij, dij, dkw, dkb, dvw, dvb, vec);

    cudaStreamWaitEvent(0, eVec, 0);
    out_kernel<<<NB_N64, 256, SM_OUT>>>(ow, ob, out);

    cudaEventDestroy(eFork);
    cudaEventDestroy(eZero);
    cudaEventDestroy(eVec);
    cudaStreamDestroy(s2);
}

// round 16
// speedup vs baseline: 1.0437x; 1.0437x over previous
#include <cuda_runtime.h>
#include <math.h>

#define N_NODES 20000
#define N_EDGES 200000
#define HCH 128
#define NB_NODE 625      // 20000/32
#define NB_N64 313       // ceil(20000/64)
#define NB_E8 25000      // 200000/8

typedef unsigned long long ull;

// ---------------- scratch (device globals; allocation-free) ----------------
// g_v uses SECTION-MAJOR layout: [node][s*128 + h*16 + d] (s = x|v1|v2)
__device__ __align__(16) float g_q[N_NODES * HCH];
__device__ __align__(16) float g_k[N_NODES * HCH];
__device__ __align__(16) float g_v[N_NODES * 3 * HCH];
__device__ __align__(16) float g_vec3[N_NODES * 3 * HCH];
__device__ __align__(16) float g_vdot[N_NODES * HCH];
__device__ __align__(16) float g_xagg[N_NODES * HCH];
__device__ __align__(16) float g_vagg[N_NODES * 3 * HCH];

__device__ __forceinline__ float silu_f(float v) {
    return v / (1.f + __expf(-v));
}
__device__ __forceinline__ float cutoff_f(float r) {
    return (r < 10.f) ? 0.5f * (__cosf(r * 0.31415926535897931f) + 1.f) : 0.f;
}

// ---- packed f32x2 helpers ----
__device__ __forceinline__ ull pack2(float x, float y) {
    ull r; asm("mov.b64 %0, {%1, %2};" : "=l"(r) : "f"(x), "f"(y)); return r;
}
__device__ __forceinline__ float2 unpack2(ull v) {
    float x, y; asm("mov.b64 {%0, %1}, %2;" : "=f"(x), "=f"(y) : "l"(v));
    return make_float2(x, y);
}
__device__ __forceinline__ void ffma2(ull& a, ull b, ull c) {
    asm("fma.rn.f32x2 %0, %1, %2, %0;" : "+l"(a) : "l"(b), "l"(c));
}
__device__ __forceinline__ void red4(float* p, float4 v) {
    asm volatile("red.global.add.v4.f32 [%0], {%1, %2, %3, %4};"
                 :: "l"(p), "f"(v.x), "f"(v.y), "f"(v.z), "f"(v.w) : "memory");
}

// ---- double-buffered weight staging: 32x128 chunk via registers ----
__device__ __forceinline__ void ldgW(float4* t, const float* __restrict__ W,
                                     int kc, int ld, int coff, int tid) {
    #pragma unroll
    for (int i = 0; i < 4; i++) {
        int idx = tid + i * 256;
        int r = idx >> 5, c4 = idx & 31;
        t[i] = *reinterpret_cast<const float4*>(&W[(kc + r) * ld + coff + c4 * 4]);
    }
}
__device__ __forceinline__ void stsW(float* sB, const float4* t, int tid) {
    #pragma unroll
    for (int i = 0; i < 4; i++)
        reinterpret_cast<float4*>(sB)[tid + i * 256] = t[i];
}

// packed inner loop: 32 k-steps, 16 cols, ONE node
__device__ __forceinline__ void gemm16p32(const float* __restrict__ aRow,
                                          int kc, const float* __restrict__ sB,
                                          int c0, ull* acc) {
    #pragma unroll 4
    for (int k = 0; k < 32; k++) {
        float a = aRow[kc + k];
        ull a2 = pack2(a, a);
        const ulonglong2* b4 =
            reinterpret_cast<const ulonglong2*>(sB + k * 128 + c0);
        ulonglong2 q0 = b4[0], q1 = b4[1], q2 = b4[2], q3 = b4[3];
        ffma2(acc[0], a2, q0.x); ffma2(acc[1], a2, q0.y);
        ffma2(acc[2], a2, q1.x); ffma2(acc[3], a2, q1.y);
        ffma2(acc[4], a2, q2.x); ffma2(acc[5], a2, q2.y);
        ffma2(acc[6], a2, q3.x); ffma2(acc[7], a2, q3.y);
    }
}

// packed inner loop: 32 k-steps, 16 cols, TWO nodes per thread
__device__ __forceinline__ void gemm16p32x2(const float* __restrict__ aR0,
                                            const float* __restrict__ aR1,
                                            int kc, const float* __restrict__ sB,
                                            int c0, ull* accA, ull* accB) {
    #pragma unroll 2
    for (int k = 0; k < 32; k++) {
        float a = aR0[kc + k], b = aR1[kc + k];
        ull a2 = pack2(a, a), b2 = pack2(b, b);
        const ulonglong2* b4 =
            reinterpret_cast<const ulonglong2*>(sB + k * 128 + c0);
        ulonglong2 q0 = b4[0], q1 = b4[1], q2 = b4[2], q3 = b4[3];
        ffma2(accA[0], a2, q0.x); ffma2(accA[1], a2, q0.y);
        ffma2(accA[2], a2, q1.x); ffma2(accA[3], a2, q1.y);
        ffma2(accA[4], a2, q2.x); ffma2(accA[5], a2, q2.y);
        ffma2(accA[6], a2, q3.x); ffma2(accA[7], a2, q3.y);
        ffma2(accB[0], b2, q0.x); ffma2(accB[1], b2, q0.y);
        ffma2(accB[2], b2, q1.x); ffma2(accB[3], b2, q1.y);
        ffma2(accB[4], b2, q2.x); ffma2(accB[5], b2, q2.y);
        ffma2(accB[6], b2, q3.x); ffma2(accB[7], b2, q3.y);
    }
}

__device__ __forceinline__ void unpack16(const ull* acc, float* o) {
    #pragma unroll
    for (int i = 0; i < 8; i++) {
        float2 f = unpack2(acc[i]);
        o[2 * i] = f.x; o[2 * i + 1] = f.y;
    }
}

// 64-node GEMM with direct register->global stores.
// permV: remap output column block f0 -> s*128 + h*16 (section-major V).
__device__ __forceinline__ void gemm_store_direct(
    const float* __restrict__ sH, const float* __restrict__ W,
    const float* __restrict__ B, float* __restrict__ OUT, int Ctot,
    float* sB0, float* sB1, int n0, int tid, int lane, int c0, int permV) {
    for (int ct = 0; ct < Ctot; ct += 128) {
        ull acc[16];
        #pragma unroll
        for (int j = 0; j < 16; j++) acc[j] = 0ull;

        float4 t[4];
        ldgW(t, W, 0, Ctot, ct, tid);
        __syncthreads();               // prior readers of sB0 done / sH visible
        stsW(sB0, t, tid);
        #pragma unroll
        for (int kc = 0; kc < 128; kc += 32) {
            __syncthreads();
            if (kc < 96) ldgW(t, W, kc + 32, Ctot, ct, tid);
            float* cur = ((kc >> 5) & 1) ? sB1 : sB0;
            gemm16p32x2(sH + lane * 129, sH + (lane + 32) * 129, kc, cur, c0,
                        acc, acc + 8);
            if (kc < 96) stsW(((kc >> 5) & 1) ? sB0 : sB1, t, tid);
        }
        float oa[16], ob[16];
        unpack16(acc, oa);
        unpack16(acc + 8, ob);
        int na0 = n0 + lane, na1 = n0 + lane + 32;
        #pragma unroll
        for (int j = 0; j < 16; j++) {
            float bi = __ldg(&B[ct + c0 + j]);
            oa[j] += bi; ob[j] += bi;
        }
        int g0 = ct + c0;
        if (permV) {
            int h = g0 / 48, r = g0 - h * 48, s = r >> 4;
            g0 = s * 128 + h * 16;
        }
        if (na0 < N_NODES) {
            float4* d = reinterpret_cast<float4*>(OUT + na0 * Ctot + g0);
            d[0] = make_float4(oa[0], oa[1], oa[2], oa[3]);
            d[1] = make_float4(oa[4], oa[5], oa[6], oa[7]);
            d[2] = make_float4(oa[8], oa[9], oa[10], oa[11]);
            d[3] = make_float4(oa[12], oa[13], oa[14], oa[15]);
        }
        if (na1 < N_NODES) {
            float4* d = reinterpret_cast<float4*>(OUT + na1 * Ctot + g0);
            d[0] = make_float4(ob[0], ob[1], ob[2], ob[3]);
            d[1] = make_float4(ob[4], ob[5], ob[6], ob[7]);
            d[2] = make_float4(ob[8], ob[9], ob[10], ob[11]);
            d[3] = make_float4(ob[12], ob[13], ob[14], ob[15]);
        }
    }
}

// single-buffer loadB, vectorized: 4x LDG.128 + 4x STS.128 per thread
__device__ __forceinline__ void loadB32(float* sB, const float* __restrict__ W,
                                        int kc, int ld, int coff, int tid) {
    #pragma unroll
    for (int i = 0; i < 4; i++) {
        int idx = tid + i * 256;
        int r = idx >> 5, c4 = idx & 31;
        reinterpret_cast<float4*>(sB)[idx] =
            *reinterpret_cast<const float4*>(&W[(kc + r) * ld + coff + c4 * 4]);
    }
}

// ---------------- kernel 0: zero aggregation buffers ----------------
__global__ void zero_kernel() {
    int i = blockIdx.x * blockDim.x + threadIdx.x;
    int stride = gridDim.x * blockDim.x;
    float4 z = make_float4(0.f, 0.f, 0.f, 0.f);
    float4* xa = reinterpret_cast<float4*>(g_xagg);
    float4* va = reinterpret_cast<float4*>(g_vagg);
    for (int k = i; k < N_NODES * 32; k += stride) xa[k] = z;
    for (int k = i; k < N_NODES * 96; k += stride) va[k] = z;
}

// -------- kernel 1: mix MLP + LN + q/k/v. 64-node tiles, 2 nodes/thread ----
__global__ void __launch_bounds__(256, 3) node_qkv_kernel(
    const float* __restrict__ x, const float* __restrict__ na,
    const float* __restrict__ w1, const float* __restrict__ b1,
    const float* __restrict__ w2, const float* __restrict__ b2,
    const float* __restrict__ lng, const float* __restrict__ lnb,
    const float* __restrict__ qw, const float* __restrict__ qb,
    const float* __restrict__ kw, const float* __restrict__ kb,
    const float* __restrict__ vw, const float* __restrict__ vb) {
    extern __shared__ float sm[];
    float* sAH  = sm;                  // 64*129 = 8256
    float* sB0  = sm + 8256;           // 4096
    float* sB1  = sm + 12352;          // 4096
    float* sRed = sm + 16448;          // 1152

    int tid = threadIdx.x, lane = tid & 31, warp = tid >> 5;
    int c0 = warp * 16;
    int n0 = blockIdx.x * 64;

    // stage x tile: float4 loads, scalar smem scatter (ld 129)
    for (int idx = tid; idx < 2048; idx += 256) {
        int node = idx >> 5, k4 = (idx & 31) * 4;
        int gn = min(n0 + node, N_NODES - 1);
        float4 v = *reinterpret_cast<const float4*>(x + gn * 128 + k4);
        float* d = sAH + node * 129 + k4;
        d[0] = v.x; d[1] = v.y; d[2] = v.z; d[3] = v.w;
    }

    // GEMM1 pass A: h1 += x @ w1[0:128]
    ull acc[16];
    #pragma unroll
    for (int j = 0; j < 16; j++) acc[j] = 0ull;
    float4 t[4];
    ldgW(t, w1, 0, 128, 0, tid);
    stsW(sB0, t, tid);
    #pragma unroll
    for (int kc = 0; kc < 128; kc += 32) {
        __syncthreads();
        ldgW(t, w1, kc + 32, 128, 0, tid);
        float* cur = ((kc >> 5) & 1) ? sB1 : sB0;
        gemm16p32x2(sAH + lane * 129, sAH + (lane + 32) * 129, kc, cur, c0,
                    acc, acc + 8);
        stsW(((kc >> 5) & 1) ? sB0 : sB1, t, tid);
    }
    __syncthreads();
    // stage na tile into same buffer (vectorized)
    for (int idx = tid; idx < 2048; idx += 256) {
        int node = idx >> 5, k4 = (idx & 31) * 4;
        int gn = min(n0 + node, N_NODES - 1);
        float4 v = *reinterpret_cast<const float4*>(na + gn * 128 + k4);
        float* d = sAH + node * 129 + k4;
        d[0] = v.x; d[1] = v.y; d[2] = v.z; d[3] = v.w;
    }
    // GEMM1 pass B: h1 += na @ w1[128:256]
    #pragma unroll
    for (int kc = 128; kc < 256; kc += 32) {
        __syncthreads();
        if (kc < 224) ldgW(t, w1, kc + 32, 128, 0, tid);
        float* cur = ((kc >> 5) & 1) ? sB1 : sB0;
        gemm16p32x2(sAH + lane * 129, sAH + (lane + 32) * 129, kc - 128, cur,
                    c0, acc, acc + 8);
        if (kc < 224) stsW(((kc >> 5) & 1) ? sB0 : sB1, t, tid);
    }
    float ha[16], hb[16];
    unpack16(acc, ha);
    unpack16(acc + 8, hb);
    __syncthreads();
    #pragma unroll
    for (int j = 0; j < 16; j++) {
        float bi = __ldg(&b1[c0 + j]);
        sAH[lane * 129 + c0 + j] = silu_f(ha[j] + bi);
        sAH[(lane + 32) * 129 + c0 + j] = silu_f(hb[j] + bi);
    }

    // GEMM2: h = h1 @ w2 + b2
    #pragma unroll
    for (int j = 0; j < 16; j++) acc[j] = 0ull;
    ldgW(t, w2, 0, 128, 0, tid);
    stsW(sB0, t, tid);
    #pragma unroll
    for (int kc = 0; kc < 128; kc += 32) {
        __syncthreads();
        if (kc < 96) ldgW(t, w2, kc + 32, 128, 0, tid);
        float* cur = ((kc >> 5) & 1) ? sB1 : sB0;
        gemm16p32x2(sAH + lane * 129, sAH + (lane + 32) * 129, kc, cur, c0,
                    acc, acc + 8);
        if (kc < 96) stsW(((kc >> 5) & 1) ? sB0 : sB1, t, tid);
    }
    unpack16(acc, ha);
    unpack16(acc + 8, hb);
    #pragma unroll
    for (int j = 0; j < 16; j++) {
        float bi = __ldg(&b2[c0 + j]);
        ha[j] += bi; hb[j] += bi;
    }

    // LayerNorm
    float sa = 0.f, sa2 = 0.f, sb = 0.f, sb2 = 0.f;
    #pragma unroll
    for (int j = 0; j < 16; j++) {
        sa += ha[j]; sa2 += ha[j] * ha[j];
        sb += hb[j]; sb2 += hb[j] * hb[j];
    }
    sRed[warp * 64 + lane] = sa;
    sRed[warp * 64 + 32 + lane] = sb;
    sRed[512 + warp * 64 + lane] = sa2;
    sRed[512 + warp * 64 + 32 + lane] = sb2;
    __syncthreads();
    if (tid < 64) {
        float ss = 0.f, qq = 0.f;
        #pragma unroll
        for (int w = 0; w < 8; w++) {
            ss += sRed[w * 64 + tid];
            qq += sRed[512 + w * 64 + tid];
        }
        float mu = ss * (1.f / 128.f);
        float var = qq * (1.f / 128.f) - mu * mu;
        sRed[1024 + tid] = mu;
        sRed[1088 + tid] = rsqrtf(var + 1e-5f);
    }
    __syncthreads();
    {
        float mua = sRed[1024 + lane], rsa = sRed[1088 + lane];
        float mub = sRed[1024 + 32 + lane], rsb = sRed[1088 + 32 + lane];
        #pragma unroll
        for (int j = 0; j < 16; j++) {
            float g = __ldg(&lng[c0 + j]), bi = __ldg(&lnb[c0 + j]);
            sAH[lane * 129 + c0 + j] = (ha[j] - mua) * rsa * g + bi;
            sAH[(lane + 32) * 129 + c0 + j] = (hb[j] - mub) * rsb * g + bi;
        }
    }

    gemm_store_direct(sAH, qw, qb, g_q, 128, sB0, sB1, n0, tid, lane, c0, 0);
    gemm_store_direct(sAH, kw, kb, g_k, 128, sB0, sB1, n0, tid, lane, c0, 0);
    gemm_store_direct(sAH, vw, vb, g_v, 384, sB0, sB1, n0, tid, lane, c0, 1);
}

// ---------------- kernel 2: vec projection -> vec_dot, vec3 (66KB) --------
__global__ void __launch_bounds__(256) node_vec_kernel(
    const float* __restrict__ vec, const float* __restrict__ vecw) {
    extern __shared__ float sm[];
    float* sA = sm;                // 96*129 = 12384
    float* sB = sA + 12384;        // 4096

    int tid = threadIdx.x, lane = tid & 31, warp = tid >> 5;
    int c0 = warp * 16;
    int n0 = blockIdx.x * 32;

    // stage vec tile: float4 loads, scalar smem scatter
    for (int idx = tid; idx < 3072; idx += 256) {
        int node = idx / 96;
        int rem = (idx - node * 96) * 4;
        int c = rem >> 7, k = rem & 127;
        float4 v =
            *reinterpret_cast<const float4*>(vec + (n0 + node) * 384 + rem);
        float* d = sA + (c * 32 + node) * 129 + k;
        d[0] = v.x; d[1] = v.y; d[2] = v.z; d[3] = v.w;
    }

    float vp1[3][16];

    for (int reg = 0; reg < 3; reg++) {
        ull acc[3][8];
        #pragma unroll
        for (int c = 0; c < 3; c++)
            #pragma unroll
            for (int j = 0; j < 8; j++) acc[c][j] = 0ull;

        for (int kc = 0; kc < 128; kc += 32) {
            __syncthreads();
            loadB32(sB, vecw, kc, 384, reg * 128, tid);
            __syncthreads();
            #pragma unroll 2
            for (int k = 0; k < 32; k++) {
                float f0 = sA[(0 * 32 + lane) * 129 + kc + k];
                float f1 = sA[(1 * 32 + lane) * 129 + kc + k];
                float f2v = sA[(2 * 32 + lane) * 129 + kc + k];
                ull a0 = pack2(f0, f0), a1 = pack2(f1, f1), a2 = pack2(f2v, f2v);
                const ulonglong2* b4 =
                    reinterpret_cast<const ulonglong2*>(sB + k * 128 + c0);
                ulonglong2 q0 = b4[0], q1 = b4[1], q2 = b4[2], q3 = b4[3];
                ffma2(acc[0][0], a0, q0.x); ffma2(acc[0][1], a0, q0.y);
                ffma2(acc[0][2], a0, q1.x); ffma2(acc[0][3], a0, q1.y);
                ffma2(acc[0][4], a0, q2.x); ffma2(acc[0][5], a0, q2.y);
                ffma2(acc[0][6], a0, q3.x); ffma2(acc[0][7], a0, q3.y);
                ffma2(acc[1][0], a1, q0.x); ffma2(acc[1][1], a1, q0.y);
                ffma2(acc[1][2], a1, q1.x); ffma2(acc[1][3], a1, q1.y);
                ffma2(acc[1][4], a1, q2.x); ffma2(acc[1][5], a1, q2.y);
                ffma2(acc[1][6], a1, q3.x); ffma2(acc[1][7], a1, q3.y);
                ffma2(acc[2][0], a2, q0.x); ffma2(acc[2][1], a2, q0.y);
                ffma2(acc[2][2], a2, q1.x); ffma2(acc[2][3], a2, q1.y);
                ffma2(acc[2][4], a2, q2.x); ffma2(acc[2][5], a2, q2.y);
                ffma2(acc[2][6], a2, q3.x); ffma2(acc[2][7], a2, q3.y);
            }
        }

        float af[3][16];
        unpack16(acc[0], af[0]);
        unpack16(acc[1], af[1]);
        unpack16(acc[2], af[2]);

        if (reg == 0) {
            #pragma unroll
            for (int c = 0; c < 3; c++)
                #pragma unroll
                for (int j = 0; j < 16; j++) vp1[c][j] = af[c][j];
        } else if (reg == 1) {
            float vd[16];
            #pragma unroll
            for (int j = 0; j < 16; j++)
                vd[j] = vp1[0][j] * af[0][j] + vp1[1][j] * af[1][j] +
                        vp1[2][j] * af[2][j];
            float4* dst =
                reinterpret_cast<float4*>(g_vdot + (n0 + lane) * 128 + c0);
            dst[0] = make_float4(vd[0], vd[1], vd[2], vd[3]);
            dst[1] = make_float4(vd[4], vd[5], vd[6], vd[7]);
            dst[2] = make_float4(vd[8], vd[9], vd[10], vd[11]);
            dst[3] = make_float4(vd[12], vd[13], vd[14], vd[15]);
        } else {
            // vec3: direct register->global float4 stores (own node = lane)
            #pragma unroll
            for (int c = 0; c < 3; c++) {
                float4* dst = reinterpret_cast<float4*>(
                    g_vec3 + (n0 + lane) * 384 + c * 128 + c0);
                dst[0] = make_float4(af[c][0], af[c][1], af[c][2], af[c][3]);
                dst[1] = make_float4(af[c][4], af[c][5], af[c][6], af[c][7]);
                dst[2] = make_float4(af[c][8], af[c][9], af[c][10], af[c][11]);
                dst[3] = make_float4(af[c][12], af[c][13], af[c][14], af[c][15]);
            }
        }
    }
}

// ---------------- kernel 3: edges (section-major v/dv reads) --------------
__global__ void __launch_bounds__(128) edge_kernel(
    const int* __restrict__ ei, const float* __restrict__ rij,
    const float* __restrict__ fij, const float* __restrict__ dij,
    const float* __restrict__ dkw, const float* __restrict__ dkb,
    const float* __restrict__ dvw, const float* __restrict__ dvb,
    const float* __restrict__ vec) {
    __shared__ __align__(16) float sDK[8 * 128];   // 4096 B
    __shared__ __align__(16) float sDV[8 * 384];   // 12288 B (first 4KB = sF2)
    __shared__ int sJ[8], sI[8];
    __shared__ float sR[8];
    __shared__ float sD[8][3];

    ull* sF2 = reinterpret_cast<ull*>(sDV);        // alias: 512 ull = 4096 B

    int tid = threadIdx.x;
    int e0 = blockIdx.x * 8;

    for (int idx = tid; idx < 512; idx += 128) {
        int r = idx >> 3, e = idx & 7;
        float f = fij[(e0 + e) * 64 + r];
        sF2[idx] = pack2(f, f);
    }
    if (tid < 8) {
        sJ[tid] = ei[e0 + tid];
        sI[tid] = ei[N_EDGES + e0 + tid];
        sR[tid] = rij[e0 + tid];
    }
    if (tid < 24) sD[tid / 3][tid % 3] = dij[e0 * 3 + tid];
    __syncthreads();

    // phase 1: fused (dk|dv) GEMM: 64 x 512, thread owns 4 output channels.
    ull acc[16];
    #pragma unroll
    for (int j = 0; j < 16; j++) acc[j] = 0ull;

    const float* wbase;
    int wstr;
    if (tid < 32) { wbase = dkw + tid * 4; wstr = 128; }
    else          { wbase = dvw + (tid - 32) * 4; wstr = 384; }

    #pragma unroll 2
    for (int r = 0; r < 64; r++) {
        ulonglong2 w =
            *reinterpret_cast<const ulonglong2*>(wbase + r * wstr);
        const ulonglong2* fp2 =
            reinterpret_cast<const ulonglong2*>(&sF2[r * 8]);
        #pragma unroll
        for (int ep = 0; ep < 4; ep++) {
            ulonglong2 ff = fp2[ep];
            ffma2(acc[2 * ep],     ff.x, w.x);
            ffma2(acc[8 + 2 * ep], ff.x, w.y);
            ffma2(acc[2 * ep + 1],     ff.y, w.x);
            ffma2(acc[8 + 2 * ep + 1], ff.y, w.y);
        }
    }
    __syncthreads();   // sF2 reads done before epilogue overwrites sDV[0:4KB]

    float4 bia;
    if (tid < 32) bia = *reinterpret_cast<const float4*>(dkb + tid * 4);
    else          bia = *reinterpret_cast<const float4*>(dvb + (tid - 32) * 4);

    // dv stores remapped to section-major: f = h*48+s*16+d -> s*128+h*16+d
    int gbase = 0;
    if (tid >= 32) {
        int f = (tid - 32) * 4;
        int h = f / 48, r = f - h * 48, s = r >> 4, d = r & 15;
        gbase = s * 128 + h * 16 + d;
    }

    #pragma unroll
    for (int e = 0; e < 8; e++) {
        float2 lo = unpack2(acc[e]);
        float2 hi = unpack2(acc[8 + e]);
        float4 ov;
        ov.x = silu_f(lo.x + bia.x);
        ov.y = silu_f(lo.y + bia.y);
        ov.z = silu_f(hi.x + bia.z);
        ov.w = silu_f(hi.y + bia.w);
        if (tid < 32)
            *reinterpret_cast<float4*>(&sDK[e * 128 + tid * 4]) = ov;
        else
            *reinterpret_cast<float4*>(&sDV[e * 384 + gbase]) = ov;
    }
    __syncthreads();

    // phase 2: attention + messages + vectorized reductions (section-major)
    int lane = tid & 31;
    int ch = lane * 4;     // = head*16 + d, contiguous across warp

    #pragma unroll
    for (int es = 0; es < 2; es++) {
        int e = (tid >> 5) + es * 4;
        int j = sJ[e], i = sI[e];

        float4 q4 = *reinterpret_cast<const float4*>(g_q + i * 128 + ch);
        float4 k4 = *reinterpret_cast<const float4*>(g_k + j * 128 + ch);
        float4 dk4 = *reinterpret_cast<const float4*>(&sDK[e * 128 + ch]);
        float t = q4.x * k4.x * dk4.x + q4.y * k4.y * dk4.y +
                  q4.z * k4.z * dk4.z + q4.w * k4.w * dk4.w;
        t += __shfl_xor_sync(0xffffffffu, t, 1);
        t += __shfl_xor_sync(0xffffffffu, t, 2);
        float attn = silu_f(t) * cutoff_f(sR[e]);

        const float* vb = g_v + j * 384;   // section-major
        float4 v0 = *reinterpret_cast<const float4*>(vb + ch);
        float4 v1 = *reinterpret_cast<const float4*>(vb + 128 + ch);
        float4 v2 = *reinterpret_cast<const float4*>(vb + 256 + ch);
        float4 dv0 = *reinterpret_cast<const float4*>(&sDV[e * 384 + ch]);
        float4 dv1 = *reinterpret_cast<const float4*>(&sDV[e * 384 + 128 + ch]);
        float4 dv2 = *reinterpret_cast<const float4*>(&sDV[e * 384 + 256 + ch]);

        float4 xm;
        xm.x = v0.x * dv0.x * attn; xm.y = v0.y * dv0.y * attn;
        xm.z = v0.z * dv0.z * attn; xm.w = v0.w * dv0.w * attn;
        red4(g_xagg + i * 128 + ch, xm);

        float4 v1m, v2m;
        v1m.x = v1.x * dv1.x; v1m.y = v1.y * dv1.y;
        v1m.z = v1.z * dv1.z; v1m.w = v1.w * dv1.w;
        v2m.x = v2.x * dv2.x; v2m.y = v2.y * dv2.y;
        v2m.z = v2.z * dv2.z; v2m.w = v2.w * dv2.w;

        const float* vecb = vec + j * 384;
        #pragma unroll
        for (int c = 0; c < 3; c++) {
            float dc = sD[e][c];
            float4 vc =
                *reinterpret_cast<const float4*>(vecb + c * 128 + ch);
            float4 m;
            m.x = vc.x * v1m.x + v2m.x * dc;
            m.y = vc.y * v1m.y + v2m.y * dc;
            m.z = vc.z * v1m.z + v2m.z * dc;
            m.w = vc.w * v1m.w + v2m.w * dc;
            red4(g_vagg + i * 384 + c * 128 + ch, m);
        }
    }
}

// ---------------- kernel 4: output (R14 version: 32-node, 66KB) -----------
__global__ void __launch_bounds__(256) out_kernel(
    const float* __restrict__ ow, const float* __restrict__ ob,
    float* __restrict__ out) {
    extern __shared__ float sm[];
    float* sA   = sm;                 // 4128 (xagg)
    float* sVDt = sm + 4128;          // 4128
    float* sO1  = sm + 8256;          // 4128
    float* sB   = sm + 12384;         // 4096

    int tid = threadIdx.x, lane = tid & 31, warp = tid >> 5;
    int c0 = warp * 16;
    int n0 = blockIdx.x * 32;

    for (int idx = tid; idx < 32 * 128; idx += 256) {
        int node = idx >> 7, col = idx & 127;
        sA[node * 129 + col] = g_xagg[(n0 + node) * 128 + col];
        sVDt[node * 129 + col] = g_vdot[(n0 + node) * 128 + col];
    }

    float o[3][16];
    for (int reg = 0; reg < 3; reg++) {
        ull acc[8];
        #pragma unroll
        for (int j = 0; j < 8; j++) acc[j] = 0ull;
        for (int kc = 0; kc < 128; kc += 32) {
            __syncthreads();
            loadB32(sB, ow, kc, 384, reg * 128, tid);
            __syncthreads();
            gemm16p32(sA + lane * 129, kc, sB, c0, acc);
        }
        float of[16];
        unpack16(acc, of);
        #pragma unroll
        for (int j = 0; j < 16; j++)
            o[reg][j] = of[j] + __ldg(&ob[reg * 128 + c0 + j]);
    }

    // dx: straight from registers (own node = lane)
    {
        float dx[16];
        #pragma unroll
        for (int j = 0; j < 16; j++)
            dx[j] = sVDt[lane * 129 + c0 + j] * o[1][j] + o[2][j];
        float4* dst = reinterpret_cast<float4*>(out + (n0 + lane) * 128 + c0);
        dst[0] = make_float4(dx[0], dx[1], dx[2], dx[3]);
        dst[1] = make_float4(dx[4], dx[5], dx[6], dx[7]);
        dst[2] = make_float4(dx[8], dx[9], dx[10], dx[11]);
        dst[3] = make_float4(dx[12], dx[13], dx[14], dx[15]);
    }

    // o1 shared for dvec
    #pragma unroll
    for (int j = 0; j < 16; j++)
        sO1[lane * 129 + c0 + j] = o[0][j];
    __syncthreads();

    // dvec
    const int base = N_NODES * 128;
    for (int idx = tid; idx < 32 * 384; idx += 256) {
        int node = idx / 384;
        int rem = idx - node * 384;
        int col = rem & 127;
        int g = (n0 + node) * 384 + rem;
        out[base + g] = g_vec3[g] * sO1[node * 129 + col] + g_vagg[g];
    }
}

// ---------------- launch ----------------
extern "C" void kernel_launch(void* const* d_in, const int* in_sizes, int n_in,
                              void* d_out, int out_size) {
    const float* x    = (const float*)d_in[0];
    const float* vec  = (const float*)d_in[1];
    const float* na   = (const float*)d_in[2];
    const int*   ei   = (const int*)d_in[3];
    const float* rij  = (const float*)d_in[4];
    const float* fij  = (const float*)d_in[5];
    const float* dij  = (const float*)d_in[6];
    const float* w1   = (const float*)d_in[7];
    const float* b1   = (const float*)d_in[8];
    const float* w2   = (const float*)d_in[9];
    const float* b2   = (const float*)d_in[10];
    const float* lng  = (const float*)d_in[11];
    const float* lnb  = (const float*)d_in[12];
    const float* qw   = (const float*)d_in[13];
    const float* qb   = (const float*)d_in[14];
    const float* kw   = (const float*)d_in[15];
    const float* kb   = (const float*)d_in[16];
    const float* vw   = (const float*)d_in[17];
    const float* vb   = (const float*)d_in[18];
    const float* ow   = (const float*)d_in[19];
    const float* ob   = (const float*)d_in[20];
    const float* vecw = (const float*)d_in[21];
    const float* dkw  = (const float*)d_in[22];
    const float* dkb  = (const float*)d_in[23];
    const float* dvw  = (const float*)d_in[24];
    const float* dvb  = (const float*)d_in[25];
    float* out = (float*)d_out;

    const int SM_QKV = (8256 + 4096 + 4096 + 1152) * 4;  // 70400
    const int SM_VEC = (12384 + 4096) * 4;               // 65920
    const int SM_OUT = (12384 + 4096) * 4;               // 65920

    cudaFuncSetAttribute(node_qkv_kernel,
                         cudaFuncAttributeMaxDynamicSharedMemorySize, SM_QKV);
    cudaFuncSetAttribute(node_vec_kernel,
                         cudaFuncAttributeMaxDynamicSharedMemorySize, SM_VEC);
    cudaFuncSetAttribute(out_kernel,
                         cudaFuncAttributeMaxDynamicSharedMemorySize, SM_OUT);

    // R9 schedule (best): s2 runs zero then node_vec concurrent with qkv.
    cudaStream_t s2;
    cudaStreamCreateWithFlags(&s2, cudaStreamNonBlocking);
    cudaEvent_t eFork, eZero, eVec;
    cudaEventCreateWithFlags(&eFork, cudaEventDisableTiming);
    cudaEventCreateWithFlags(&eZero, cudaEventDisableTiming);
    cudaEventCreateWithFlags(&eVec, cudaEventDisableTiming);

    cudaEventRecord(eFork, 0);
    cudaStreamWaitEvent(s2, eFork, 0);
    zero_kernel<<<2560, 256, 0, s2>>>();
    cudaEventRecord(eZero, s2);
    node_vec_kernel<<<NB_NODE, 256, SM_VEC, s2>>>(vec, vecw);
    cudaEventRecord(eVec, s2);

    node_qkv_kernel<<<NB_N64, 256, SM_QKV>>>(x, na, w1, b1, w2, b2, lng, lnb,
                                             qw, qb, kw, kb, vw, vb);
    cudaStreamWaitEvent(0, eZero, 0);
    edge_kernel<<<NB_E8, 128>>>(ei, rij, fij, dij, dkw, dkb, dvw, dvb, vec);

    cudaStreamWaitEvent(0, eVec, 0);
    out_kernel<<<NB_NODE, 256, SM_OUT>>>(ow, ob, out);

    cudaEventDestroy(eFork);
    cudaEventDestroy(eZero);
    cudaEventDestroy(eVec);
    cudaStreamDestroy(s2);
}

// round 17
// speedup vs baseline: 1.1026x; 1.0564x over previous
#include <cuda_runtime.h>
#include <math.h>

#define N_NODES 20000
#define N_EDGES 200000
#define HCH 128
#define NB_NODE 625      // 20000/32
#define NB_N64 313       // ceil(20000/64)
#define NB_E16 12500     // 200000/16

typedef unsigned long long ull;
typedef unsigned int uint32;

// ---------------- scratch (device globals; allocation-free) ----------------
// g_v uses SECTION-MAJOR layout: [node][s*128 + h*16 + d] (s = x|v1|v2)
__device__ __align__(16) float g_q[N_NODES * HCH];
__device__ __align__(16) float g_k[N_NODES * HCH];
__device__ __align__(16) float g_v[N_NODES * 3 * HCH];
__device__ __align__(16) float g_vec3[N_NODES * 3 * HCH];
__device__ __align__(16) float g_vdot[N_NODES * HCH];
__device__ __align__(16) float g_xagg[N_NODES * HCH];
__device__ __align__(16) float g_vagg[N_NODES * 3 * HCH];
__device__ __align__(16) uint32 g_wt[64 * 512];   // tf32 bits: [r][dk|dv]

__device__ __forceinline__ float silu_f(float v) {
    return v / (1.f + __expf(-v));
}
__device__ __forceinline__ float cutoff_f(float r) {
    return (r < 10.f) ? 0.5f * (__cosf(r * 0.31415926535897931f) + 1.f) : 0.f;
}

// ---- packed f32x2 helpers ----
__device__ __forceinline__ ull pack2(float x, float y) {
    ull r; asm("mov.b64 %0, {%1, %2};" : "=l"(r) : "f"(x), "f"(y)); return r;
}
__device__ __forceinline__ float2 unpack2(ull v) {
    float x, y; asm("mov.b64 {%0, %1}, %2;" : "=f"(x), "=f"(y) : "l"(v));
    return make_float2(x, y);
}
__device__ __forceinline__ void ffma2(ull& a, ull b, ull c) {
    asm("fma.rn.f32x2 %0, %1, %2, %0;" : "+l"(a) : "l"(b), "l"(c));
}
__device__ __forceinline__ void red4(float* p, float4 v) {
    asm volatile("red.global.add.v4.f32 [%0], {%1, %2, %3, %4};"
                 :: "l"(p), "f"(v.x), "f"(v.y), "f"(v.z), "f"(v.w) : "memory");
}
__device__ __forceinline__ uint32 to_tf32(float v) {
    uint32 t; asm("cvt.rna.tf32.f32 %0, %1;" : "=r"(t) : "f"(v)); return t;
}
__device__ __forceinline__ void mma_tf32(float* d, uint32 a0, uint32 a1,
                                         uint32 a2, uint32 a3,
                                         uint32 b0, uint32 b1) {
    asm volatile(
        "mma.sync.aligned.m16n8k8.row.col.f32.tf32.tf32.f32 "
        "{%0,%1,%2,%3}, {%4,%5,%6,%7}, {%8,%9}, {%0,%1,%2,%3};"
        : "+f"(d[0]), "+f"(d[1]), "+f"(d[2]), "+f"(d[3])
        : "r"(a0), "r"(a1), "r"(a2), "r"(a3), "r"(b0), "r"(b1));
}

// ---- double-buffered weight staging: 32x128 chunk via registers ----
__device__ __forceinline__ void ldgW(float4* t, const float* __restrict__ W,
                                     int kc, int ld, int coff, int tid) {
    #pragma unroll
    for (int i = 0; i < 4; i++) {
        int idx = tid + i * 256;
        int r = idx >> 5, c4 = idx & 31;
        t[i] = *reinterpret_cast<const float4*>(&W[(kc + r) * ld + coff + c4 * 4]);
    }
}
__device__ __forceinline__ void stsW(float* sB, const float4* t, int tid) {
    #pragma unroll
    for (int i = 0; i < 4; i++)
        reinterpret_cast<float4*>(sB)[tid + i * 256] = t[i];
}

// packed inner loop: 32 k-steps, 16 cols, ONE node
__device__ __forceinline__ void gemm16p32(const float* __restrict__ aRow,
                                          int kc, const float* __restrict__ sB,
                                          int c0, ull* acc) {
    #pragma unroll 4
    for (int k = 0; k < 32; k++) {
        float a = aRow[kc + k];
        ull a2 = pack2(a, a);
        const ulonglong2* b4 =
            reinterpret_cast<const ulonglong2*>(sB + k * 128 + c0);
        ulonglong2 q0 = b4[0], q1 = b4[1], q2 = b4[2], q3 = b4[3];
        ffma2(acc[0], a2, q0.x); ffma2(acc[1], a2, q0.y);
        ffma2(acc[2], a2, q1.x); ffma2(acc[3], a2, q1.y);
        ffma2(acc[4], a2, q2.x); ffma2(acc[5], a2, q2.y);
        ffma2(acc[6], a2, q3.x); ffma2(acc[7], a2, q3.y);
    }
}

// packed inner loop: 32 k-steps, 16 cols, TWO nodes per thread
__device__ __forceinline__ void gemm16p32x2(const float* __restrict__ aR0,
                                            const float* __restrict__ aR1,
                                            int kc, const float* __restrict__ sB,
                                            int c0, ull* accA, ull* accB) {
    #pragma unroll 2
    for (int k = 0; k < 32; k++) {
        float a = aR0[kc + k], b = aR1[kc + k];
        ull a2 = pack2(a, a), b2 = pack2(b, b);
        const ulonglong2* b4 =
            reinterpret_cast<const ulonglong2*>(sB + k * 128 + c0);
        ulonglong2 q0 = b4[0], q1 = b4[1], q2 = b4[2], q3 = b4[3];
        ffma2(accA[0], a2, q0.x); ffma2(accA[1], a2, q0.y);
        ffma2(accA[2], a2, q1.x); ffma2(accA[3], a2, q1.y);
        ffma2(accA[4], a2, q2.x); ffma2(accA[5], a2, q2.y);
        ffma2(accA[6], a2, q3.x); ffma2(accA[7], a2, q3.y);
        ffma2(accB[0], b2, q0.x); ffma2(accB[1], b2, q0.y);
        ffma2(accB[2], b2, q1.x); ffma2(accB[3], b2, q1.y);
        ffma2(accB[4], b2, q2.x); ffma2(accB[5], b2, q2.y);
        ffma2(accB[6], b2, q3.x); ffma2(accB[7], b2, q3.y);
    }
}

__device__ __forceinline__ void unpack16(const ull* acc, float* o) {
    #pragma unroll
    for (int i = 0; i < 8; i++) {
        float2 f = unpack2(acc[i]);
        o[2 * i] = f.x; o[2 * i + 1] = f.y;
    }
}

// 64-node GEMM with direct register->global stores.
__device__ __forceinline__ void gemm_store_direct(
    const float* __restrict__ sH, const float* __restrict__ W,
    const float* __restrict__ B, float* __restrict__ OUT, int Ctot,
    float* sB0, float* sB1, int n0, int tid, int lane, int c0, int permV) {
    for (int ct = 0; ct < Ctot; ct += 128) {
        ull acc[16];
        #pragma unroll
        for (int j = 0; j < 16; j++) acc[j] = 0ull;

        float4 t[4];
        ldgW(t, W, 0, Ctot, ct, tid);
        __syncthreads();
        stsW(sB0, t, tid);
        #pragma unroll
        for (int kc = 0; kc < 128; kc += 32) {
            __syncthreads();
            if (kc < 96) ldgW(t, W, kc + 32, Ctot, ct, tid);
            float* cur = ((kc >> 5) & 1) ? sB1 : sB0;
            gemm16p32x2(sH + lane * 129, sH + (lane + 32) * 129, kc, cur, c0,
                        acc, acc + 8);
            if (kc < 96) stsW(((kc >> 5) & 1) ? sB0 : sB1, t, tid);
        }
        float oa[16], ob[16];
        unpack16(acc, oa);
        unpack16(acc + 8, ob);
        int na0 = n0 + lane, na1 = n0 + lane + 32;
        #pragma unroll
        for (int j = 0; j < 16; j++) {
            float bi = __ldg(&B[ct + c0 + j]);
            oa[j] += bi; ob[j] += bi;
        }
        int g0 = ct + c0;
        if (permV) {
            int h = g0 / 48, r = g0 - h * 48, s = r >> 4;
            g0 = s * 128 + h * 16;
        }
        if (na0 < N_NODES) {
            float4* d = reinterpret_cast<float4*>(OUT + na0 * Ctot + g0);
            d[0] = make_float4(oa[0], oa[1], oa[2], oa[3]);
            d[1] = make_float4(oa[4], oa[5], oa[6], oa[7]);
            d[2] = make_float4(oa[8], oa[9], oa[10], oa[11]);
            d[3] = make_float4(oa[12], oa[13], oa[14], oa[15]);
        }
        if (na1 < N_NODES) {
            float4* d = reinterpret_cast<float4*>(OUT + na1 * Ctot + g0);
            d[0] = make_float4(ob[0], ob[1], ob[2], ob[3]);
            d[1] = make_float4(ob[4], ob[5], ob[6], ob[7]);
            d[2] = make_float4(ob[8], ob[9], ob[10], ob[11]);
            d[3] = make_float4(ob[12], ob[13], ob[14], ob[15]);
        }
    }
}

// single-buffer loadB, vectorized
__device__ __forceinline__ void loadB32(float* sB, const float* __restrict__ W,
                                        int kc, int ld, int coff, int tid) {
    #pragma unroll
    for (int i = 0; i < 4; i++) {
        int idx = tid + i * 256;
        int r = idx >> 5, c4 = idx & 31;
        reinterpret_cast<float4*>(sB)[idx] =
            *reinterpret_cast<const float4*>(&W[(kc + r) * ld + coff + c4 * 4]);
    }
}

// ---------------- kernel 0a: weights -> tf32 (once per launch) ------------
__global__ void wt_prep_kernel(const float* __restrict__ dkw,
                               const float* __restrict__ dvw) {
    int i = blockIdx.x * 256 + threadIdx.x;
    if (i < 64 * 512) {
        int r = i >> 9, c = i & 511;
        float v = (c < 128) ? dkw[r * 128 + c] : dvw[r * 384 + (c - 128)];
        g_wt[i] = to_tf32(v);
    }
}

// ---------------- kernel 0: zero aggregation buffers ----------------
__global__ void zero_kernel() {
    int i = blockIdx.x * blockDim.x + threadIdx.x;
    int stride = gridDim.x * blockDim.x;
    float4 z = make_float4(0.f, 0.f, 0.f, 0.f);
    float4* xa = reinterpret_cast<float4*>(g_xagg);
    float4* va = reinterpret_cast<float4*>(g_vagg);
    for (int k = i; k < N_NODES * 32; k += stride) xa[k] = z;
    for (int k = i; k < N_NODES * 96; k += stride) va[k] = z;
}

// -------- kernel 1: mix MLP + LN + q/k/v (unchanged from R16 best) --------
__global__ void __launch_bounds__(256, 3) node_qkv_kernel(
    const float* __restrict__ x, const float* __restrict__ na,
    const float* __restrict__ w1, const float* __restrict__ b1,
    const float* __restrict__ w2, const float* __restrict__ b2,
    const float* __restrict__ lng, const float* __restrict__ lnb,
    const float* __restrict__ qw, const float* __restrict__ qb,
    const float* __restrict__ kw, const float* __restrict__ kb,
    const float* __restrict__ vw, const float* __restrict__ vb) {
    extern __shared__ float sm[];
    float* sAH  = sm;                  // 64*129 = 8256
    float* sB0  = sm + 8256;           // 4096
    float* sB1  = sm + 12352;          // 4096
    float* sRed = sm + 16448;          // 1152

    int tid = threadIdx.x, lane = tid & 31, warp = tid >> 5;
    int c0 = warp * 16;
    int n0 = blockIdx.x * 64;

    for (int idx = tid; idx < 2048; idx += 256) {
        int node = idx >> 5, k4 = (idx & 31) * 4;
        int gn = min(n0 + node, N_NODES - 1);
        float4 v = *reinterpret_cast<const float4*>(x + gn * 128 + k4);
        float* d = sAH + node * 129 + k4;
        d[0] = v.x; d[1] = v.y; d[2] = v.z; d[3] = v.w;
    }

    ull acc[16];
    #pragma unroll
    for (int j = 0; j < 16; j++) acc[j] = 0ull;
    float4 t[4];
    ldgW(t, w1, 0, 128, 0, tid);
    stsW(sB0, t, tid);
    #pragma unroll
    for (int kc = 0; kc < 128; kc += 32) {
        __syncthreads();
        ldgW(t, w1, kc + 32, 128, 0, tid);
        float* cur = ((kc >> 5) & 1) ? sB1 : sB0;
        gemm16p32x2(sAH + lane * 129, sAH + (lane + 32) * 129, kc, cur, c0,
                    acc, acc + 8);
        stsW(((kc >> 5) & 1) ? sB0 : sB1, t, tid);
    }
    __syncthreads();
    for (int idx = tid; idx < 2048; idx += 256) {
        int node = idx >> 5, k4 = (idx & 31) * 4;
        int gn = min(n0 + node, N_NODES - 1);
        float4 v = *reinterpret_cast<const float4*>(na + gn * 128 + k4);
        float* d = sAH + node * 129 + k4;
        d[0] = v.x; d[1] = v.y; d[2] = v.z; d[3] = v.w;
    }
    #pragma unroll
    for (int kc = 128; kc < 256; kc += 32) {
        __syncthreads();
        if (kc < 224) ldgW(t, w1, kc + 32, 128, 0, tid);
        float* cur = ((kc >> 5) & 1) ? sB1 : sB0;
        gemm16p32x2(sAH + lane * 129, sAH + (lane + 32) * 129, kc - 128, cur,
                    c0, acc, acc + 8);
        if (kc < 224) stsW(((kc >> 5) & 1) ? sB0 : sB1, t, tid);
    }
    float ha[16], hb[16];
    unpack16(acc, ha);
    unpack16(acc + 8, hb);
    __syncthreads();
    #pragma unroll
    for (int j = 0; j < 16; j++) {
        float bi = __ldg(&b1[c0 + j]);
        sAH[lane * 129 + c0 + j] = silu_f(ha[j] + bi);
        sAH[(lane + 32) * 129 + c0 + j] = silu_f(hb[j] + bi);
    }

    #pragma unroll
    for (int j = 0; j < 16; j++) acc[j] = 0ull;
    ldgW(t, w2, 0, 128, 0, tid);
    stsW(sB0, t, tid);
    #pragma unroll
    for (int kc = 0; kc < 128; kc += 32) {
        __syncthreads();
        if (kc < 96) ldgW(t, w2, kc + 32, 128, 0, tid);
        float* cur = ((kc >> 5) & 1) ? sB1 : sB0;
        gemm16p32x2(sAH + lane * 129, sAH + (lane + 32) * 129, kc, cur, c0,
                    acc, acc + 8);
        if (kc < 96) stsW(((kc >> 5) & 1) ? sB0 : sB1, t, tid);
    }
    unpack16(acc, ha);
    unpack16(acc + 8, hb);
    #pragma unroll
    for (int j = 0; j < 16; j++) {
        float bi = __ldg(&b2[c0 + j]);
        ha[j] += bi; hb[j] += bi;
    }

    float sa = 0.f, sa2 = 0.f, sb = 0.f, sb2 = 0.f;
    #pragma unroll
    for (int j = 0; j < 16; j++) {
        sa += ha[j]; sa2 += ha[j] * ha[j];
        sb += hb[j]; sb2 += hb[j] * hb[j];
    }
    sRed[warp * 64 + lane] = sa;
    sRed[warp * 64 + 32 + lane] = sb;
    sRed[512 + warp * 64 + lane] = sa2;
    sRed[512 + warp * 64 + 32 + lane] = sb2;
    __syncthreads();
    if (tid < 64) {
        float ss = 0.f, qq = 0.f;
        #pragma unroll
        for (int w = 0; w < 8; w++) {
            ss += sRed[w * 64 + tid];
            qq += sRed[512 + w * 64 + tid];
        }
        float mu = ss * (1.f / 128.f);
        float var = qq * (1.f / 128.f) - mu * mu;
        sRed[1024 + tid] = mu;
        sRed[1088 + tid] = rsqrtf(var + 1e-5f);
    }
    __syncthreads();
    {
        float mua = sRed[1024 + lane], rsa = sRed[1088 + lane];
        float mub = sRed[1024 + 32 + lane], rsb = sRed[1088 + 32 + lane];
        #pragma unroll
        for (int j = 0; j < 16; j++) {
            float g = __ldg(&lng[c0 + j]), bi = __ldg(&lnb[c0 + j]);
            sAH[lane * 129 + c0 + j] = (ha[j] - mua) * rsa * g + bi;
            sAH[(lane + 32) * 129 + c0 + j] = (hb[j] - mub) * rsb * g + bi;
        }
    }

    gemm_store_direct(sAH, qw, qb, g_q, 128, sB0, sB1, n0, tid, lane, c0, 0);
    gemm_store_direct(sAH, kw, kb, g_k, 128, sB0, sB1, n0, tid, lane, c0, 0);
    gemm_store_direct(sAH, vw, vb, g_v, 384, sB0, sB1, n0, tid, lane, c0, 1);
}

// ---------------- kernel 2: vec projection (unchanged from R16) -----------
__global__ void __launch_bounds__(256) node_vec_kernel(
    const float* __restrict__ vec, const float* __restrict__ vecw) {
    extern __shared__ float sm[];
    float* sA = sm;                // 96*129 = 12384
    float* sB = sA + 12384;        // 4096

    int tid = threadIdx.x, lane = tid & 31, warp = tid >> 5;
    int c0 = warp * 16;
    int n0 = blockIdx.x * 32;

    for (int idx = tid; idx < 3072; idx += 256) {
        int node = idx / 96;
        int rem = (idx - node * 96) * 4;
        int c = rem >> 7, k = rem & 127;
        float4 v =
            *reinterpret_cast<const float4*>(vec + (n0 + node) * 384 + rem);
        float* d = sA + (c * 32 + node) * 129 + k;
        d[0] = v.x; d[1] = v.y; d[2] = v.z; d[3] = v.w;
    }

    float vp1[3][16];

    for (int reg = 0; reg < 3; reg++) {
        ull acc[3][8];
        #pragma unroll
        for (int c = 0; c < 3; c++)
            #pragma unroll
            for (int j = 0; j < 8; j++) acc[c][j] = 0ull;

        for (int kc = 0; kc < 128; kc += 32) {
            __syncthreads();
            loadB32(sB, vecw, kc, 384, reg * 128, tid);
            __syncthreads();
            #pragma unroll 2
            for (int k = 0; k < 32; k++) {
                float f0 = sA[(0 * 32 + lane) * 129 + kc + k];
                float f1 = sA[(1 * 32 + lane) * 129 + kc + k];
                float f2v = sA[(2 * 32 + lane) * 129 + kc + k];
                ull a0 = pack2(f0, f0), a1 = pack2(f1, f1), a2 = pack2(f2v, f2v);
                const ulonglong2* b4 =
                    reinterpret_cast<const ulonglong2*>(sB + k * 128 + c0);
                ulonglong2 q0 = b4[0], q1 = b4[1], q2 = b4[2], q3 = b4[3];
                ffma2(acc[0][0], a0, q0.x); ffma2(acc[0][1], a0, q0.y);
                ffma2(acc[0][2], a0, q1.x); ffma2(acc[0][3], a0, q1.y);
                ffma2(acc[0][4], a0, q2.x); ffma2(acc[0][5], a0, q2.y);
                ffma2(acc[0][6], a0, q3.x); ffma2(acc[0][7], a0, q3.y);
                ffma2(acc[1][0], a1, q0.x); ffma2(acc[1][1], a1, q0.y);
                ffma2(acc[1][2], a1, q1.x); ffma2(acc[1][3], a1, q1.y);
                ffma2(acc[1][4], a1, q2.x); ffma2(acc[1][5], a1, q2.y);
                ffma2(acc[1][6], a1, q3.x); ffma2(acc[1][7], a1, q3.y);
                ffma2(acc[2][0], a2, q0.x); ffma2(acc[2][1], a2, q0.y);
                ffma2(acc[2][2], a2, q1.x); ffma2(acc[2][3], a2, q1.y);
                ffma2(acc[2][4], a2, q2.x); ffma2(acc[2][5], a2, q2.y);
                ffma2(acc[2][6], a2, q3.x); ffma2(acc[2][7], a2, q3.y);
            }
        }

        float af[3][16];
        unpack16(acc[0], af[0]);
        unpack16(acc[1], af[1]);
        unpack16(acc[2], af[2]);

        if (reg == 0) {
            #pragma unroll
            for (int c = 0; c < 3; c++)
                #pragma unroll
                for (int j = 0; j < 16; j++) vp1[c][j] = af[c][j];
        } else if (reg == 1) {
            float vd[16];
            #pragma unroll
            for (int j = 0; j < 16; j++)
                vd[j] = vp1[0][j] * af[0][j] + vp1[1][j] * af[1][j] +
                        vp1[2][j] * af[2][j];
            float4* dst =
                reinterpret_cast<float4*>(g_vdot + (n0 + lane) * 128 + c0);
            dst[0] = make_float4(vd[0], vd[1], vd[2], vd[3]);
            dst[1] = make_float4(vd[4], vd[5], vd[6], vd[7]);
            dst[2] = make_float4(vd[8], vd[9], vd[10], vd[11]);
            dst[3] = make_float4(vd[12], vd[13], vd[14], vd[15]);
        } else {
            #pragma unroll
            for (int c = 0; c < 3; c++) {
                float4* dst = reinterpret_cast<float4*>(
                    g_vec3 + (n0 + lane) * 384 + c * 128 + c0);
                dst[0] = make_float4(af[c][0], af[c][1], af[c][2], af[c][3]);
                dst[1] = make_float4(af[c][4], af[c][5], af[c][6], af[c][7]);
                dst[2] = make_float4(af[c][8], af[c][9], af[c][10], af[c][11]);
                dst[3] = make_float4(af[c][12], af[c][13], af[c][14], af[c][15]);
            }
        }
    }
}

// -------- kernel 3: edges. Phase-1 = tf32 mma (16 edges, 256 thr) ---------
// Warp w owns channels [w*64, w*64+64). M=16 edges, N=8 per mma, K=8.
__global__ void __launch_bounds__(256) edge_kernel(
    const int* __restrict__ ei, const float* __restrict__ rij,
    const float* __restrict__ fij, const float* __restrict__ dij,
    const float* __restrict__ dkb, const float* __restrict__ dvb,
    const float* __restrict__ vec) {
    extern __shared__ char smx[];
    uint32* sW  = reinterpret_cast<uint32*>(smx);            // 8*520 = 16640B
    uint32* sFt = reinterpret_cast<uint32*>(smx + 16640);    // 16*68 = 4352B
    float*  sDK = reinterpret_cast<float*>(smx + 20992);     // 16*128 = 8192B
    float*  sDV = reinterpret_cast<float*>(smx + 29184);     // 16*384 = 24576B
    int*    sJ  = reinterpret_cast<int*>(smx + 53760);       // 16
    int*    sI  = sJ + 16;
    float*  sR  = reinterpret_cast<float*>(sI + 16);
    float*  sD  = sR + 16;                                   // 48

    int tid = threadIdx.x;
    int w = tid >> 5, lane = tid & 31;
    int t4 = lane & 3, g = lane >> 2;
    int e0 = blockIdx.x * 16;

    // stage f (cvt to tf32) + meta
    for (int idx = tid; idx < 1024; idx += 256) {
        int e = idx >> 6, r = idx & 63;
        sFt[e * 68 + r] = to_tf32(fij[e0 * 64 + idx]);
    }
    if (tid < 16) {
        sJ[tid] = ei[e0 + tid];
        sI[tid] = ei[N_EDGES + e0 + tid];
        sR[tid] = rij[e0 + tid];
    }
    if (tid < 48) sD[tid] = dij[e0 * 3 + tid];
    __syncthreads();

    // phase 1: (16 edges) x (512 channels) = f[16x64] @ W[64x512] on tensor
    float acc[8][4];
    #pragma unroll
    for (int nt = 0; nt < 8; nt++)
        #pragma unroll
        for (int j = 0; j < 4; j++) acc[nt][j] = 0.f;

    for (int ks = 0; ks < 8; ks++) {
        if (ks) __syncthreads();       // prior sW reads done
        // stage W rows ks*8 .. ks*8+7 (tf32 bits, pad-8 rows)
        #pragma unroll
        for (int i = 0; i < 4; i++) {
            int idx = tid + i * 256;   // 0..1023 -> 8 rows x 128 uint4
            int r = idx >> 7, c4 = (idx & 127) << 2;
            uint4 v = *reinterpret_cast<const uint4*>(
                &g_wt[(ks * 8 + r) * 512 + c4]);
            *reinterpret_cast<uint4*>(&sW[r * 520 + c4]) = v;
        }
        __syncthreads();

        // A fragments (f): reused across all 8 n-tiles
        int kb = ks * 8;
        uint32 a0 = sFt[g * 68 + kb + t4];
        uint32 a1 = sFt[(g + 8) * 68 + kb + t4];
        uint32 a2 = sFt[g * 68 + kb + t4 + 4];
        uint32 a3 = sFt[(g + 8) * 68 + kb + t4 + 4];

        #pragma unroll
        for (int nt = 0; nt < 8; nt++) {
            int cb = w * 64 + nt * 8;
            uint32 b0 = sW[t4 * 520 + cb + g];
            uint32 b1 = sW[(t4 + 4) * 520 + cb + g];
            mma_tf32(acc[nt], a0, a1, a2, a3, b0, b1);
        }
    }

    // epilogue: bias + silu -> sDK / sDV (section-major)
    #pragma unroll
    for (int nt = 0; nt < 8; nt++) {
        int ch0 = w * 64 + nt * 8 + 2 * t4;
        float b0v, b1v;
        if (ch0 < 128) {
            b0v = __ldg(&dkb[ch0]); b1v = __ldg(&dkb[ch0 + 1]);
        } else {
            b0v = __ldg(&dvb[ch0 - 128]); b1v = __ldg(&dvb[ch0 - 127]);
        }
        float v00 = silu_f(acc[nt][0] + b0v);   // (edge g,   ch0)
        float v01 = silu_f(acc[nt][1] + b1v);   // (edge g,   ch0+1)
        float v10 = silu_f(acc[nt][2] + b0v);   // (edge g+8, ch0)
        float v11 = silu_f(acc[nt][3] + b1v);
        if (ch0 < 128) {
            *reinterpret_cast<float2*>(&sDK[g * 128 + ch0]) =
                make_float2(v00, v01);
            *reinterpret_cast<float2*>(&sDK[(g + 8) * 128 + ch0]) =
                make_float2(v10, v11);
        } else {
            int f = ch0 - 128;
            int h = (f * 683) >> 15;           // f / 48
            int rr = f - h * 48;
            int gb = ((rr >> 4) << 7) + h * 16 + (rr & 15);
            *reinterpret_cast<float2*>(&sDV[g * 384 + gb]) =
                make_float2(v00, v01);
            *reinterpret_cast<float2*>(&sDV[(g + 8) * 384 + gb]) =
                make_float2(v10, v11);
        }
    }
    __syncthreads();

    // phase 2: attention + messages + reductions (8 warps x 2 edges)
    int ch = lane * 4;     // head*16 + d, contiguous

    #pragma unroll
    for (int es = 0; es < 2; es++) {
        int e = w + es * 8;
        int j = sJ[e], i = sI[e];

        float4 q4 = *reinterpret_cast<const float4*>(g_q + i * 128 + ch);
        float4 k4 = *reinterpret_cast<const float4*>(g_k + j * 128 + ch);
        float4 dk4 = *reinterpret_cast<const float4*>(&sDK[e * 128 + ch]);
        float t = q4.x * k4.x * dk4.x + q4.y * k4.y * dk4.y +
                  q4.z * k4.z * dk4.z + q4.w * k4.w * dk4.w;
        t += __shfl_xor_sync(0xffffffffu, t, 1);
        t += __shfl_xor_sync(0xffffffffu, t, 2);
        float attn = silu_f(t) * cutoff_f(sR[e]);

        const float* vb = g_v + j * 384;   // section-major
        float4 v0 = *reinterpret_cast<const float4*>(vb + ch);
        float4 v1 = *reinterpret_cast<const float4*>(vb + 128 + ch);
        float4 v2 = *reinterpret_cast<const float4*>(vb + 256 + ch);
        float4 dv0 = *reinterpret_cast<const float4*>(&sDV[e * 384 + ch]);
        float4 dv1 = *reinterpret_cast<const float4*>(&sDV[e * 384 + 128 + ch]);
        float4 dv2 = *reinterpret_cast<const float4*>(&sDV[e * 384 + 256 + ch]);

        float4 xm;
        xm.x = v0.x * dv0.x * attn; xm.y = v0.y * dv0.y * attn;
        xm.z = v0.z * dv0.z * attn; xm.w = v0.w * dv0.w * attn;
        red4(g_xagg + i * 128 + ch, xm);

        float4 v1m, v2m;
        v1m.x = v1.x * dv1.x; v1m.y = v1.y * dv1.y;
        v1m.z = v1.z * dv1.z; v1m.w = v1.w * dv1.w;
        v2m.x = v2.x * dv2.x; v2m.y = v2.y * dv2.y;
        v2m.z = v2.z * dv2.z; v2m.w = v2.w * dv2.w;

        const float* vecb = vec + j * 384;
        #pragma unroll
        for (int c = 0; c < 3; c++) {
            float dc = sD[e * 3 + c];
            float4 vc =
                *reinterpret_cast<const float4*>(vecb + c * 128 + ch);
            float4 m;
            m.x = vc.x * v1m.x + v2m.x * dc;
            m.y = vc.y * v1m.y + v2m.y * dc;
            m.z = vc.z * v1m.z + v2m.z * dc;
            m.w = vc.w * v1m.w + v2m.w * dc;
            red4(g_vagg + i * 384 + c * 128 + ch, m);
        }
    }
}

// ---------------- kernel 4: output (unchanged from R16) -------------------
__global__ void __launch_bounds__(256) out_kernel(
    const float* __restrict__ ow, const float* __restrict__ ob,
    float* __restrict__ out) {
    extern __shared__ float sm[];
    float* sA   = sm;                 // 4128 (xagg)
    float* sVDt = sm + 4128;          // 4128
    float* sO1  = sm + 8256;          // 4128
    float* sB   = sm + 12384;         // 4096

    int tid = threadIdx.x, lane = tid & 31, warp = tid >> 5;
    int c0 = warp * 16;
    int n0 = blockIdx.x * 32;

    for (int idx = tid; idx < 32 * 128; idx += 256) {
        int node = idx >> 7, col = idx & 127;
        sA[node * 129 + col] = g_xagg[(n0 + node) * 128 + col];
        sVDt[node * 129 + col] = g_vdot[(n0 + node) * 128 + col];
    }

    float o[3][16];
    for (int reg = 0; reg < 3; reg++) {
        ull acc[8];
        #pragma unroll
        for (int j = 0; j < 8; j++) acc[j] = 0ull;
        for (int kc = 0; kc < 128; kc += 32) {
            __syncthreads();
            loadB32(sB, ow, kc, 384, reg * 128, tid);
            __syncthreads();
            gemm16p32(sA + lane * 129, kc, sB, c0, acc);
        }
        float of[16];
        unpack16(acc, of);
        #pragma unroll
        for (int j = 0; j < 16; j++)
            o[reg][j] = of[j] + __ldg(&ob[reg * 128 + c0 + j]);
    }

    {
        float dx[16];
        #pragma unroll
        for (int j = 0; j < 16; j++)
            dx[j] = sVDt[lane * 129 + c0 + j] * o[1][j] + o[2][j];
        float4* dst = reinterpret_cast<float4*>(out + (n0 + lane) * 128 + c0);
        dst[0] = make_float4(dx[0], dx[1], dx[2], dx[3]);
        dst[1] = make_float4(dx[4], dx[5], dx[6], dx[7]);
        dst[2] = make_float4(dx[8], dx[9], dx[10], dx[11]);
        dst[3] = make_float4(dx[12], dx[13], dx[14], dx[15]);
    }

    #pragma unroll
    for (int j = 0; j < 16; j++)
        sO1[lane * 129 + c0 + j] = o[0][j];
    __syncthreads();

    const int base = N_NODES * 128;
    for (int idx = tid; idx < 32 * 384; idx += 256) {
        int node = idx / 384;
        int rem = idx - node * 384;
        int col = rem & 127;
        int g = (n0 + node) * 384 + rem;
        out[base + g] = g_vec3[g] * sO1[node * 129 + col] + g_vagg[g];
    }
}

// ---------------- launch ----------------
extern "C" void kernel_launch(void* const* d_in, const int* in_sizes, int n_in,
                              void* d_out, int out_size) {
    const float* x    = (const float*)d_in[0];
    const float* vec  = (const float*)d_in[1];
    const float* na   = (const float*)d_in[2];
    const int*   ei   = (const int*)d_in[3];
    const float* rij  = (const float*)d_in[4];
    const float* fij  = (const float*)d_in[5];
    const float* dij  = (const float*)d_in[6];
    const float* w1   = (const float*)d_in[7];
    const float* b1   = (const float*)d_in[8];
    const float* w2   = (const float*)d_in[9];
    const float* b2   = (const float*)d_in[10];
    const float* lng  = (const float*)d_in[11];
    const float* lnb  = (const float*)d_in[12];
    const float* qw   = (const float*)d_in[13];
    const float* qb   = (const float*)d_in[14];
    const float* kw   = (const float*)d_in[15];
    const float* kb   = (const float*)d_in[16];
    const float* vw   = (const float*)d_in[17];
    const float* vb   = (const float*)d_in[18];
    const float* ow   = (const float*)d_in[19];
    const float* ob   = (const float*)d_in[20];
    const float* vecw = (const float*)d_in[21];
    const float* dkw  = (const float*)d_in[22];
    const float* dkb  = (const float*)d_in[23];
    const float* dvw  = (const float*)d_in[24];
    const float* dvb  = (const float*)d_in[25];
    float* out = (float*)d_out;

    const int SM_QKV  = (8256 + 4096 + 4096 + 1152) * 4;  // 70400
    const int SM_VEC  = (12384 + 4096) * 4;               // 65920
    const int SM_OUT  = (12384 + 4096) * 4;               // 65920
    const int SM_EDGE = 53760 + 384;                      // 54144

    cudaFuncSetAttribute(node_qkv_kernel,
                         cudaFuncAttributeMaxDynamicSharedMemorySize, SM_QKV);
    cudaFuncSetAttribute(node_vec_kernel,
                         cudaFuncAttributeMaxDynamicSharedMemorySize, SM_VEC);
    cudaFuncSetAttribute(out_kernel,
                         cudaFuncAttributeMaxDynamicSharedMemorySize, SM_OUT);
    cudaFuncSetAttribute(edge_kernel,
                         cudaFuncAttributeMaxDynamicSharedMemorySize, SM_EDGE);

    // R9 schedule; wt_prep precedes zero on s2, edge waits on eZero (covers it)
    cudaStream_t s2;
    cudaStreamCreateWithFlags(&s2, cudaStreamNonBlocking);
    cudaEvent_t eFork, eZero, eVec;
    cudaEventCreateWithFlags(&eFork, cudaEventDisableTiming);
    cudaEventCreateWithFlags(&eZero, cudaEventDisableTiming);
    cudaEventCreateWithFlags(&eVec, cudaEventDisableTiming);

    cudaEventRecord(eFork, 0);
    cudaStreamWaitEvent(s2, eFork, 0);
    wt_prep_kernel<<<128, 256, 0, s2>>>(dkw, dvw);
    zero_kernel<<<2560, 256, 0, s2>>>();
    cudaEventRecord(eZero, s2);
    node_vec_kernel<<<NB_NODE, 256, SM_VEC, s2>>>(vec, vecw);
    cudaEventRecord(eVec, s2);

    node_qkv_kernel<<<NB_N64, 256, SM_QKV>>>(x, na, w1, b1, w2, b2, lng, lnb,
                                             qw, qb, kw, kb, vw, vb);
    cudaStreamWaitEvent(0, eZero, 0);
    edge_kernel<<<NB_E16, 256, SM_EDGE>>>(ei, rij, fij, dij, dkb, dvb, vec);

    cudaStreamWaitEvent(0, eVec, 0);
    out_kernel<<<NB_NODE, 256, SM_OUT>>>(ow, ob, out);

    cudaEventDestroy(eFork);
    cudaEventDestroy(eZero);
    cudaEventDestroy(eVec);
    cudaStreamDestroy(s2);
}